// round 1
// baseline (speedup 1.0000x reference)
#include <cuda_runtime.h>

// Problem constants (fixed shapes per reference)
constexpr int B = 4, L = 4096, H = 16, D = 64, M = 256, E = 64;
constexpr int BH = B * H;            // 64
constexpr int NCHUNK = 16;           // L-chunks for kernel 1
constexpr int LCHUNK = L / NCHUNK;   // 256
constexpr int LT = 64;               // inner L tile
constexpr int NTILE = LCHUNK / LT;   // 4
constexpr float SCALE = 0.35355339059327378f;  // 64^-0.25
constexpr float KEPS = 1e-3f;
constexpr float ZEPS = 1e-6f;

// Scratch (static device allocations are the sanctioned workaround)
__device__ float g_KVpart[(size_t)NCHUNK * BH * M * E];  // 64 MB
__device__ float g_Kspart[(size_t)NCHUNK * BH * M];      // 1 MB
__device__ float g_KV[(size_t)BH * M * E];               // 4 MB
__device__ float g_Ksum[(size_t)BH * M];

extern __shared__ float smem[];

// phi: sF[l][m] = relu( sum_d sX[l][d] * sPt[d][m] ) + KEPS
// sX is pre-scaled by SCALE. 512 threads: warp w -> rows [4w,4w+4), lane -> 8 m's.
__device__ __forceinline__ void phi_compute(const float* __restrict__ sPt,
                                            const float* __restrict__ sX,
                                            float* __restrict__ sF, int tid) {
    const int w = tid >> 5;
    const int lane = tid & 31;
    const int m0 = lane * 8;
    float acc[4][8];
#pragma unroll
    for (int i = 0; i < 4; i++)
#pragma unroll
        for (int j = 0; j < 8; j++) acc[i][j] = 0.f;

#pragma unroll 8
    for (int d = 0; d < D; d++) {
        float4 pa = *(const float4*)(sPt + d * M + m0);
        float4 pb = *(const float4*)(sPt + d * M + m0 + 4);
        float p[8] = {pa.x, pa.y, pa.z, pa.w, pb.x, pb.y, pb.z, pb.w};
#pragma unroll
        for (int i = 0; i < 4; i++) {
            float xv = sX[(w * 4 + i) * D + d];
#pragma unroll
            for (int j = 0; j < 8; j++) acc[i][j] = fmaf(xv, p[j], acc[i][j]);
        }
    }
#pragma unroll
    for (int i = 0; i < 4; i++) {
        float4 o0, o1;
        o0.x = fmaxf(acc[i][0], 0.f) + KEPS;
        o0.y = fmaxf(acc[i][1], 0.f) + KEPS;
        o0.z = fmaxf(acc[i][2], 0.f) + KEPS;
        o0.w = fmaxf(acc[i][3], 0.f) + KEPS;
        o1.x = fmaxf(acc[i][4], 0.f) + KEPS;
        o1.y = fmaxf(acc[i][5], 0.f) + KEPS;
        o1.z = fmaxf(acc[i][6], 0.f) + KEPS;
        o1.w = fmaxf(acc[i][7], 0.f) + KEPS;
        *(float4*)(sF + (w * 4 + i) * M + m0) = o0;
        *(float4*)(sF + (w * 4 + i) * M + m0 + 4) = o1;
    }
}

__device__ __forceinline__ void load_Pt(const float* __restrict__ P, float* __restrict__ sPt,
                                        int tid) {
    // sPt[d][m] = P[m][d]; float4 global reads, conflict-free smem writes.
    for (int j = tid; j < M * D / 4; j += 512) {
        int m = j & (M - 1);
        int d4 = j >> 8;  // 0..15
        float4 val = *(const float4*)(P + m * D + d4 * 4);
        sPt[(d4 * 4 + 0) * M + m] = val.x;
        sPt[(d4 * 4 + 1) * M + m] = val.y;
        sPt[(d4 * 4 + 2) * M + m] = val.z;
        sPt[(d4 * 4 + 3) * M + m] = val.w;
    }
}

// Kernel 1: per (b,h,chunk) partial KV[M,E] and Ksum[M]
__global__ __launch_bounds__(512) void kv_kernel(const float* __restrict__ k,
                                                 const float* __restrict__ v,
                                                 const float* __restrict__ P) {
    float* sPt = smem;           // 16384
    float* sK = smem + 16384;    // 4096
    float* sV = smem + 20480;    // 4096
    float* sF = smem + 24576;    // 16384
    const int tid = threadIdx.x;
    const int bh = blockIdx.x;
    const int b = bh / H, h = bh % H;
    const int chunk = blockIdx.y;

    load_Pt(P, sPt, tid);

    float cacc[8][4];
#pragma unroll
    for (int i = 0; i < 8; i++)
#pragma unroll
        for (int j = 0; j < 4; j++) cacc[i][j] = 0.f;
    float ksum = 0.f;
    const int m0c = (tid >> 4) * 8;  // 0..248
    const int e0c = (tid & 15) * 4;  // 0..60

    for (int it = 0; it < NTILE; it++) {
        const int lbase = chunk * LCHUNK + it * LT;
        __syncthreads();  // protects sK/sV/sF reuse (also orders Pt on first iter)
        for (int j = tid; j < LT * D; j += 512) {
            int l = j >> 6, d = j & 63;
            size_t idx = ((size_t)((b * L + lbase + l) * H + h)) * D + d;
            sK[j] = k[idx] * SCALE;
            sV[j] = v[idx];
        }
        __syncthreads();
        phi_compute(sPt, sK, sF, tid);
        __syncthreads();
        // KV accumulation: cacc[mi][ei] += Kf[l][m0c+mi] * V[l][e0c+ei]
#pragma unroll 4
        for (int l = 0; l < LT; l++) {
            float4 vv = *(const float4*)(sV + l * E + e0c);
            float4 ka = *(const float4*)(sF + l * M + m0c);
            float4 kb = *(const float4*)(sF + l * M + m0c + 4);
            float km[8] = {ka.x, ka.y, ka.z, ka.w, kb.x, kb.y, kb.z, kb.w};
#pragma unroll
            for (int mi = 0; mi < 8; mi++) {
                cacc[mi][0] = fmaf(km[mi], vv.x, cacc[mi][0]);
                cacc[mi][1] = fmaf(km[mi], vv.y, cacc[mi][1]);
                cacc[mi][2] = fmaf(km[mi], vv.z, cacc[mi][2]);
                cacc[mi][3] = fmaf(km[mi], vv.w, cacc[mi][3]);
            }
        }
        if (tid < M) {
            float s = 0.f;
#pragma unroll 8
            for (int l = 0; l < LT; l++) s += sF[l * M + tid];
            ksum += s;
        }
    }
    float* dst = g_KVpart + (size_t)(chunk * BH + bh) * M * E;
#pragma unroll
    for (int mi = 0; mi < 8; mi++) {
        float4 o = {cacc[mi][0], cacc[mi][1], cacc[mi][2], cacc[mi][3]};
        *(float4*)(dst + (m0c + mi) * E + e0c) = o;
    }
    if (tid < M) g_Kspart[(size_t)(chunk * BH + bh) * M + tid] = ksum;
}

// Kernel 2: deterministic 16-way reduction of partials
__global__ void reduce_kernel() {
    int idx = blockIdx.x * blockDim.x + threadIdx.x;
    if (idx < BH * M * E) {
        float s = 0.f;
#pragma unroll
        for (int c = 0; c < NCHUNK; c++) s += g_KVpart[(size_t)c * BH * M * E + idx];
        g_KV[idx] = s;
    }
    if (idx < BH * M) {
        float s = ZEPS;
#pragma unroll
        for (int c = 0; c < NCHUNK; c++) s += g_Kspart[(size_t)c * BH * M + idx];
        g_Ksum[idx] = s;
    }
}

// Kernel 3: per (b,h, 64-row Q tile): phi(Q), Z, out = (Qf@KV)*Z
__global__ __launch_bounds__(512) void out_kernel(const float* __restrict__ q,
                                                  const float* __restrict__ P,
                                                  float* __restrict__ out) {
    float* sPt = smem;            // 16384
    float* sKV = smem + 16384;    // 16384
    float* sQ = smem + 32768;     // 4096
    float* sF = smem + 36864;     // 16384
    float* sKs = smem + 53248;    // 256
    float* sZ = smem + 53504;     // 64
    const int tid = threadIdx.x;
    const int bh = blockIdx.x;
    const int b = bh / H, h = bh % H;
    const int lbase = blockIdx.y * LT;

    load_Pt(P, sPt, tid);
    const float* kvsrc = g_KV + (size_t)bh * M * E;
    for (int j = tid; j < M * E; j += 512) sKV[j] = kvsrc[j];
    if (tid < M) sKs[tid] = g_Ksum[(size_t)bh * M + tid];
    for (int j = tid; j < LT * D; j += 512) {
        int l = j >> 6, d = j & 63;
        sQ[j] = q[((size_t)((b * L + lbase + l) * H + h)) * D + d] * SCALE;
    }
    __syncthreads();
    phi_compute(sPt, sQ, sF, tid);
    __syncthreads();
    // Z: warp w handles l in [4w, 4w+4)
    {
        int w = tid >> 5, lane = tid & 31;
#pragma unroll
        for (int li = 0; li < 4; li++) {
            int l = w * 4 + li;
            float s = 0.f;
#pragma unroll
            for (int j = 0; j < 8; j++) {
                int m = lane + j * 32;
                s += sF[l * M + m] * sKs[m];
            }
#pragma unroll
            for (int o = 16; o > 0; o >>= 1) s += __shfl_xor_sync(0xffffffffu, s, o);
            if (lane == 0) sZ[l] = 1.0f / s;
        }
    }
    __syncthreads();
    // out GEMM: thread tile 4 l x 2 e
    const int l0 = (tid >> 5) * 4;   // whole warp shares l0 -> broadcast Qf loads
    const int e0 = (tid & 31) * 2;
    float oacc[4][2];
#pragma unroll
    for (int i = 0; i < 4; i++) { oacc[i][0] = 0.f; oacc[i][1] = 0.f; }
#pragma unroll 8
    for (int m = 0; m < M; m++) {
        float2 kv = *(const float2*)(sKV + m * E + e0);
#pragma unroll
        for (int i = 0; i < 4; i++) {
            float qv = sF[(l0 + i) * M + m];
            oacc[i][0] = fmaf(qv, kv.x, oacc[i][0]);
            oacc[i][1] = fmaf(qv, kv.y, oacc[i][1]);
        }
    }
#pragma unroll
    for (int i = 0; i < 4; i++) {
        int lg = lbase + l0 + i;
        float z = sZ[l0 + i];
        float2 o = {oacc[i][0] * z, oacc[i][1] * z};
        *(float2*)(out + ((size_t)((b * L + lg) * H + h)) * E + e0) = o;
    }
}

extern "C" void kernel_launch(void* const* d_in, const int* in_sizes, int n_in,
                              void* d_out, int out_size) {
    const float* q = (const float*)d_in[0];
    const float* k = (const float*)d_in[1];
    const float* v = (const float*)d_in[2];
    const float* P = (const float*)d_in[3];
    float* out = (float*)d_out;

    constexpr int SMEM1 = (16384 + 4096 + 4096 + 16384) * 4;          // 163840
    constexpr int SMEM3 = (16384 + 16384 + 4096 + 16384 + 256 + 64) * 4;  // 214272

    cudaFuncSetAttribute(kv_kernel, cudaFuncAttributeMaxDynamicSharedMemorySize, SMEM1);
    cudaFuncSetAttribute(out_kernel, cudaFuncAttributeMaxDynamicSharedMemorySize, SMEM3);

    kv_kernel<<<dim3(BH, NCHUNK), 512, SMEM1>>>(k, v, P);
    reduce_kernel<<<(BH * M * E + 255) / 256, 256>>>();
    out_kernel<<<dim3(BH, L / LT), 512, SMEM3>>>(q, P, out);
}

// round 3
// speedup vs baseline: 3.3728x; 3.3728x over previous
#include <cuda_runtime.h>
#include <cuda_fp16.h>
#include <cstdint>

constexpr int B = 4, L = 4096, H = 16, D = 64, M = 256, E = 64;
constexpr int BH = 64;
constexpr int NCHUNK = 16;   // grid.y for both big kernels
constexpr int TILES = 2;     // 128-row tiles per CTA
constexpr float SCALE = 0.35355339059327378f;  // 64^-0.25
constexpr float KEPS = 1e-3f;
constexpr float ZEPS = 1e-6f;

// ---- global scratch ----
__device__ float g_KVpart[(size_t)NCHUNK * BH * M * E];  // 64 MB
__device__ float g_Kspart[(size_t)NCHUNK * BH * M];
__device__ __half g_KVh[(size_t)BH * M * E];
__device__ __half g_KVl[(size_t)BH * M * E];
__device__ float g_Ksum[(size_t)BH * M];

// ---- smem byte offsets (kernel A) ----
constexpr int A_PH = 0, A_PL = 32768, A_XH = 65536, A_XL = 81920, A_VH = 98304,
              A_VL = 114688, A_FH = 131072, A_FL = 163840, A_KS = 196608;
constexpr int SMEM_A = 204800;
// ---- smem byte offsets (kernel B) ----
constexpr int B_PH = 0, B_PL = 32768, B_XH = 65536, B_XL = 81920, B_FH = 98304,
              B_FL = 131072, B_KVH = 163840, B_KVL = 180224, B_KS = 196608, B_ZP = 197632,
              B_SZ = 198656;
constexpr int SMEM_B = 199168;

// ============================ low-level helpers ============================
__device__ __forceinline__ uint32_t smem_u32(const void* p) {
    uint32_t a;
    asm("{ .reg .u64 t; cvta.to.shared.u64 t, %1; cvt.u32.u64 %0, t; }" : "=r"(a) : "l"(p));
    return a;
}
__device__ __forceinline__ void ldsm_x4(uint32_t a, uint32_t r[4]) {
    asm volatile("ldmatrix.sync.aligned.m8n8.x4.shared.b16 {%0,%1,%2,%3}, [%4];"
                 : "=r"(r[0]), "=r"(r[1]), "=r"(r[2]), "=r"(r[3]) : "r"(a));
}
__device__ __forceinline__ void ldsm_x4t(uint32_t a, uint32_t r[4]) {
    asm volatile("ldmatrix.sync.aligned.m8n8.x4.trans.shared.b16 {%0,%1,%2,%3}, [%4];"
                 : "=r"(r[0]), "=r"(r[1]), "=r"(r[2]), "=r"(r[3]) : "r"(a));
}
__device__ __forceinline__ void ldsm_x2(uint32_t a, uint32_t r[2]) {
    asm volatile("ldmatrix.sync.aligned.m8n8.x2.shared.b16 {%0,%1}, [%2];"
                 : "=r"(r[0]), "=r"(r[1]) : "r"(a));
}
__device__ __forceinline__ void ldsm_x2t(uint32_t a, uint32_t r[2]) {
    asm volatile("ldmatrix.sync.aligned.m8n8.x2.trans.shared.b16 {%0,%1}, [%2];"
                 : "=r"(r[0]), "=r"(r[1]) : "r"(a));
}
__device__ __forceinline__ void mma16816(float c[4], const uint32_t a[4], const uint32_t b[2]) {
    asm volatile(
        "mma.sync.aligned.m16n8k16.row.col.f32.f16.f16.f32 "
        "{%0,%1,%2,%3}, {%4,%5,%6,%7}, {%8,%9}, {%0,%1,%2,%3};"
        : "+f"(c[0]), "+f"(c[1]), "+f"(c[2]), "+f"(c[3])
        : "r"(a[0]), "r"(a[1]), "r"(a[2]), "r"(a[3]), "r"(b[0]), "r"(b[1]));
}
__device__ __forceinline__ uint32_t packh2(float x, float y) {
    __half2 h = __floats2half2_rn(x, y);
    return *(uint32_t*)&h;
}
// split 8 fp32 into fp16 hi/lo 16B chunks
__device__ __forceinline__ void split_store8(float4 a, float4 b, char* hp, char* lp) {
    float x[8] = {a.x, a.y, a.z, a.w, b.x, b.y, b.z, b.w};
    uint32_t h[4], l[4];
#pragma unroll
    for (int i = 0; i < 4; i++) {
        __half h0 = __float2half_rn(x[2 * i]), h1 = __float2half_rn(x[2 * i + 1]);
        float r0 = x[2 * i] - __half2float(h0), r1 = x[2 * i + 1] - __half2float(h1);
        h[i] = packh2(__half2float(h0), __half2float(h1));
        l[i] = packh2(r0, r1);
    }
    *(uint4*)hp = make_uint4(h[0], h[1], h[2], h[3]);
    *(uint4*)lp = make_uint4(l[0], l[1], l[2], l[3]);
}
// smem addr for 128B-row arrays with chunk-XOR swizzle
__device__ __forceinline__ uint32_t adr128(uint32_t base, int row, int chunk) {
    return base + row * 128 + ((chunk ^ (row & 7)) << 4);
}
// smem addr for 256B-row arrays (F tiles), chunk 0..15, XOR low 3 bits
__device__ __forceinline__ uint32_t adr256(uint32_t base, int row, int chunk) {
    return base + row * 256 + ((chunk ^ (row & 7)) << 4);
}

// phi MMA: acc[j][4] = X[lg*16..+16, 0:64] @ P[hf*128+quad*64+j*8 .. +8, 0:64]^T (3-term hi/lo)
__device__ __forceinline__ void phi_mma(uint32_t sb, int XHo, int XLo, int PHo, int PLo,
                                        float acc[8][4], int lg, int quad, int hf, int lane) {
    const int ln = lane & 7, g = lane >> 3, gB = g & 1;
    const int rowA = lg * 16 + ln + (g & 1) * 8;
    const int rowB = hf * 128 + quad * 64 + ln;
#pragma unroll
    for (int kk = 0; kk < 4; kk++) {
        uint32_t ah[4], al[4];
        int cA = (2 * kk + (g >> 1)) ^ ln;
        ldsm_x4(sb + XHo + rowA * 128 + (cA << 4), ah);
        ldsm_x4(sb + XLo + rowA * 128 + (cA << 4), al);
        int cB = (2 * kk + gB) ^ ln;
        uint32_t pbh = sb + PHo + rowB * 128 + (cB << 4);
        uint32_t pbl = sb + PLo + rowB * 128 + (cB << 4);
#pragma unroll
        for (int j = 0; j < 8; j++) {
            uint32_t bh2[2], bl2[2];
            ldsm_x2(pbh + j * 1024, bh2);
            ldsm_x2(pbl + j * 1024, bl2);
            mma16816(acc[j], ah, bh2);
            mma16816(acc[j], ah, bl2);
            mma16816(acc[j], al, bh2);
        }
    }
}

// load P scaled+split into smem (once per CTA)
__device__ __forceinline__ void load_P(const float* __restrict__ P, char* smem, uint32_t sb,
                                       int PHo, int PLo, int tid) {
    for (int u = tid; u < 2048; u += 512) {
        int m = u >> 3, ch = u & 7;
        float4 p0 = *(const float4*)(P + m * 64 + ch * 8);
        float4 p1 = *(const float4*)(P + m * 64 + ch * 8 + 4);
        p0.x *= SCALE; p0.y *= SCALE; p0.z *= SCALE; p0.w *= SCALE;
        p1.x *= SCALE; p1.y *= SCALE; p1.z *= SCALE; p1.w *= SCALE;
        uint32_t off = adr128(0, m, ch);
        split_store8(p0, p1, smem + PHo + off, smem + PLo + off);
    }
}

// ============================ Kernel A: KV + Ksum partials ============================
__global__ __launch_bounds__(512, 1) void kv_kernel(const float* __restrict__ k,
                                                    const float* __restrict__ v,
                                                    const float* __restrict__ P) {
    extern __shared__ char smem[];
    const uint32_t sb = smem_u32(smem);
    const int tid = threadIdx.x, w = tid >> 5, lane = tid & 31;
    const int ln = lane & 7, g = lane >> 3, gB = g & 1;
    const int bh = blockIdx.x, b = bh >> 4, hd = bh & 15;
    const int chunk = blockIdx.y;
    const int lg = w & 7, quad = w >> 3;  // phi roles
    const int mt = w & 7, eh = w >> 3;    // KV roles

    load_P(P, smem, sb, A_PH, A_PL, tid);
    for (int u = tid; u < 2048; u += 512) ((float*)(smem + A_KS))[u] = 0.f;

    float kvacc[2][4][4];
#pragma unroll
    for (int a = 0; a < 2; a++)
#pragma unroll
        for (int n = 0; n < 4; n++)
#pragma unroll
            for (int i = 0; i < 4; i++) kvacc[a][n][i] = 0.f;

    for (int t = 0; t < TILES; t++) {
        __syncthreads();  // prior tile consumers done (and orders P/KS on t=0)
        const int lbase = chunk * 256 + t * 128;
        const size_t gbase = ((size_t)(b * L + lbase) * H + hd) * 64;
        for (int u = tid; u < 1024; u += 512) {
            int l = u >> 3, ch = u & 7;
            size_t gi = gbase + (size_t)l * 1024 + ch * 8;
            float4 x0 = *(const float4*)(k + gi);
            float4 x1 = *(const float4*)(k + gi + 4);
            uint32_t off = adr128(0, l, ch);
            split_store8(x0, x1, smem + A_XH + off, smem + A_XL + off);
            float4 v0 = *(const float4*)(v + gi);
            float4 v1 = *(const float4*)(v + gi + 4);
            split_store8(v0, v1, smem + A_VH + off, smem + A_VL + off);
        }
        __syncthreads();

#pragma unroll
        for (int hf = 0; hf < 2; hf++) {
            float acc[8][4];
#pragma unroll
            for (int j = 0; j < 8; j++)
#pragma unroll
                for (int i = 0; i < 4; i++) acc[j][i] = 0.f;
            phi_mma(sb, A_XH, A_XL, A_PH, A_PL, acc, lg, quad, hf, lane);
            __syncthreads();  // prior F consumers done
            // relu+eps, split-store F, Ksum partials
            const int r0 = lg * 16 + (lane >> 2);
            float* sKs = (float*)(smem + A_KS);
#pragma unroll
            for (int j = 0; j < 8; j++) {
                int ml = quad * 64 + j * 8 + 2 * (lane & 3);
                float f0 = fmaxf(acc[j][0], 0.f) + KEPS;
                float f1 = fmaxf(acc[j][1], 0.f) + KEPS;
                float f2 = fmaxf(acc[j][2], 0.f) + KEPS;
                float f3 = fmaxf(acc[j][3], 0.f) + KEPS;
                // store (r0, ml..ml+1) and (r0+8, ...)
                uint32_t o0 = adr256(0, r0, ml >> 3) + (ml & 7) * 2 - sb + sb;  // byte off
                uint32_t o1 = adr256(0, r0 + 8, ml >> 3) + (ml & 7) * 2;
                o0 = adr256(0, r0, ml >> 3) + (ml & 7) * 2;
                __half h0 = __float2half_rn(f0), h1 = __float2half_rn(f1);
                __half h2 = __float2half_rn(f2), h3 = __float2half_rn(f3);
                *(uint32_t*)(smem + A_FH + o0) = packh2(__half2float(h0), __half2float(h1));
                *(uint32_t*)(smem + A_FL + o0) =
                    packh2(f0 - __half2float(h0), f1 - __half2float(h1));
                *(uint32_t*)(smem + A_FH + o1) = packh2(__half2float(h2), __half2float(h3));
                *(uint32_t*)(smem + A_FL + o1) =
                    packh2(f2 - __half2float(h2), f3 - __half2float(h3));
                float s0 = f0 + f2, s1 = f1 + f3;
#pragma unroll
                for (int ox = 4; ox <= 16; ox <<= 1) {
                    s0 += __shfl_xor_sync(0xffffffffu, s0, ox);
                    s1 += __shfl_xor_sync(0xffffffffu, s1, ox);
                }
                if (lane < 4) {
                    sKs[lg * 256 + hf * 128 + ml] += s0;
                    sKs[lg * 256 + hf * 128 + ml + 1] += s1;
                }
            }
            __syncthreads();
            // KV mma: kvacc[hf][n] += Kf^T @ V over l=0..127
#pragma unroll
            for (int kk = 0; kk < 8; kk++) {
                uint32_t ah[4], al[4];
                int rowA = kk * 16 + (g >> 1) * 8 + ln;
                int cA = (2 * mt + (g & 1)) ^ ln;
                ldsm_x4t(sb + A_FH + rowA * 256 + (cA << 4), ah);
                ldsm_x4t(sb + A_FL + rowA * 256 + (cA << 4), al);
                int rowB = kk * 16 + gB * 8 + ln;
#pragma unroll
                for (int n = 0; n < 4; n++) {
                    uint32_t bh2[2], bl2[2];
                    int cB = (eh * 4 + n) ^ ln;
                    ldsm_x2t(sb + A_VH + rowB * 128 + (cB << 4), bh2);
                    ldsm_x2t(sb + A_VL + rowB * 128 + (cB << 4), bl2);
                    mma16816(kvacc[hf][n], ah, bh2);
                    mma16816(kvacc[hf][n], ah, bl2);
                    mma16816(kvacc[hf][n], al, bh2);
                }
            }
        }
    }
    // write KV partials
    float* dst = g_KVpart + (size_t)(chunk * BH + bh) * M * E;
    const int r = lane >> 2, c2 = 2 * (lane & 3);
#pragma unroll
    for (int hf = 0; hf < 2; hf++)
#pragma unroll
        for (int n = 0; n < 4; n++) {
            int m0 = hf * 128 + mt * 16 + r;
            int e = eh * 32 + n * 8 + c2;
            *(float2*)(dst + m0 * 64 + e) = make_float2(kvacc[hf][n][0], kvacc[hf][n][1]);
            *(float2*)(dst + (m0 + 8) * 64 + e) = make_float2(kvacc[hf][n][2], kvacc[hf][n][3]);
        }
    __syncthreads();
    if (tid < 256) {
        const float* sKs = (const float*)(smem + A_KS);
        float s = 0.f;
#pragma unroll
        for (int i = 0; i < 8; i++) s += sKs[i * 256 + tid];
        g_Kspart[(size_t)(chunk * BH + bh) * M + tid] = s;
    }
}

// ============================ reduce + KV fp16 split ============================
__global__ void reduce_kernel() {
    int idx = blockIdx.x * 256 + threadIdx.x;
    if (idx < BH * M * E) {
        float s = 0.f;
#pragma unroll
        for (int c = 0; c < NCHUNK; c++) s += g_KVpart[(size_t)c * BH * M * E + idx];
        __half h = __float2half_rn(s);
        g_KVh[idx] = h;
        g_KVl[idx] = __float2half_rn(s - __half2float(h));
    }
    if (idx < BH * M) {
        float s = ZEPS;
#pragma unroll
        for (int c = 0; c < NCHUNK; c++) s += g_Kspart[(size_t)c * BH * M + idx];
        g_Ksum[idx] = s;
    }
}

// ============================ Kernel B: out = (Qf @ KV) * Z ============================
__global__ __launch_bounds__(512, 1) void out_kernel(const float* __restrict__ q,
                                                     const float* __restrict__ P,
                                                     float* __restrict__ out) {
    extern __shared__ char smem[];
    const uint32_t sb = smem_u32(smem);
    const int tid = threadIdx.x, w = tid >> 5, lane = tid & 31;
    const int ln = lane & 7, g = lane >> 3, gB = g & 1;
    const int bh = blockIdx.x, b = bh >> 4, hd = bh & 15;
    const int lg = w & 7, quad = w >> 3;  // phi roles
    const int lt = w & 7, eh = w >> 3;    // out roles

    load_P(P, smem, sb, B_PH, B_PL, tid);
    float* sKsm = (float*)(smem + B_KS);
    if (tid < 256) sKsm[tid] = g_Ksum[(size_t)bh * M + tid];

    for (int t = 0; t < TILES; t++) {
        __syncthreads();
        const int lbase = blockIdx.y * 256 + t * 128;
        const size_t gbase = ((size_t)(b * L + lbase) * H + hd) * 64;
        for (int u = tid; u < 1024; u += 512) {
            int l = u >> 3, ch = u & 7;
            size_t gi = gbase + (size_t)l * 1024 + ch * 8;
            float4 x0 = *(const float4*)(q + gi);
            float4 x1 = *(const float4*)(q + gi + 4);
            uint32_t off = adr128(0, l, ch);
            split_store8(x0, x1, smem + B_XH + off, smem + B_XL + off);
        }
        __syncthreads();

        float oacc[4][4];
#pragma unroll
        for (int n = 0; n < 4; n++)
#pragma unroll
            for (int i = 0; i < 4; i++) oacc[n][i] = 0.f;
        float zp0 = 0.f, zp1 = 0.f;

#pragma unroll
        for (int hf = 0; hf < 2; hf++) {
            float acc[8][4];
#pragma unroll
            for (int j = 0; j < 8; j++)
#pragma unroll
                for (int i = 0; i < 4; i++) acc[j][i] = 0.f;
            phi_mma(sb, B_XH, B_XL, B_PH, B_PL, acc, lg, quad, hf, lane);
            __syncthreads();
            const int r0 = lg * 16 + (lane >> 2);
#pragma unroll
            for (int j = 0; j < 8; j++) {
                int ml = quad * 64 + j * 8 + 2 * (lane & 3);
                float f0 = fmaxf(acc[j][0], 0.f) + KEPS;
                float f1 = fmaxf(acc[j][1], 0.f) + KEPS;
                float f2 = fmaxf(acc[j][2], 0.f) + KEPS;
                float f3 = fmaxf(acc[j][3], 0.f) + KEPS;
                uint32_t o0 = adr256(0, r0, ml >> 3) + (ml & 7) * 2;
                uint32_t o1 = adr256(0, r0 + 8, ml >> 3) + (ml & 7) * 2;
                __half h0 = __float2half_rn(f0), h1 = __float2half_rn(f1);
                __half h2 = __float2half_rn(f2), h3 = __float2half_rn(f3);
                *(uint32_t*)(smem + B_FH + o0) = packh2(__half2float(h0), __half2float(h1));
                *(uint32_t*)(smem + B_FL + o0) =
                    packh2(f0 - __half2float(h0), f1 - __half2float(h1));
                *(uint32_t*)(smem + B_FH + o1) = packh2(__half2float(h2), __half2float(h3));
                *(uint32_t*)(smem + B_FL + o1) =
                    packh2(f2 - __half2float(h2), f3 - __half2float(h3));
                float ks0 = sKsm[hf * 128 + ml], ks1 = sKsm[hf * 128 + ml + 1];
                zp0 += f0 * ks0 + f1 * ks1;
                zp1 += f2 * ks0 + f3 * ks1;
            }
            // load KV half (fp16 hi/lo) into smem
            for (int u = tid; u < 1024; u += 512) {
                int m = u >> 3, ch = u & 7;
                size_t gi = ((size_t)(bh * 256 + hf * 128 + m)) * 64 + ch * 8;
                uint32_t off = adr128(0, m, ch);
                *(uint4*)(smem + B_KVH + off) = *(const uint4*)(g_KVh + gi);
                *(uint4*)(smem + B_KVL + off) = *(const uint4*)(g_KVl + gi);
            }
            __syncthreads();
            // out mma: oacc[n] += Qf @ KVhalf
#pragma unroll
            for (int kk = 0; kk < 8; kk++) {
                uint32_t ah[4], al[4];
                int rowA = lt * 16 + ln + (g & 1) * 8;
                int cA = (2 * kk + (g >> 1)) ^ ln;
                ldsm_x4(sb + B_FH + rowA * 256 + (cA << 4), ah);
                ldsm_x4(sb + B_FL + rowA * 256 + (cA << 4), al);
                int rowB = kk * 16 + gB * 8 + ln;
#pragma unroll
                for (int n = 0; n < 4; n++) {
                    uint32_t bh2[2], bl2[2];
                    int cB = (eh * 4 + n) ^ ln;
                    ldsm_x2t(sb + B_KVH + rowB * 128 + (cB << 4), bh2);
                    ldsm_x2t(sb + B_KVL + rowB * 128 + (cB << 4), bl2);
                    mma16816(oacc[n], ah, bh2);
                    mma16816(oacc[n], ah, bl2);
                    mma16816(oacc[n], al, bh2);
                }
            }
            __syncthreads();  // KV/F consumed before next hf overwrites
        }
        // Z reduce
        zp0 += __shfl_xor_sync(0xffffffffu, zp0, 1);
        zp0 += __shfl_xor_sync(0xffffffffu, zp0, 2);
        zp1 += __shfl_xor_sync(0xffffffffu, zp1, 1);
        zp1 += __shfl_xor_sync(0xffffffffu, zp1, 2);
        float* sZp = (float*)(smem + B_ZP);
        if ((lane & 3) == 0) {
            sZp[quad * 128 + lg * 16 + (lane >> 2)] = zp0;
            sZp[quad * 128 + lg * 16 + (lane >> 2) + 8] = zp1;
        }
        __syncthreads();
        float* sZ = (float*)(smem + B_SZ);
        if (tid < 128) sZ[tid] = 1.0f / (sZp[tid] + sZp[128 + tid]);
        __syncthreads();
        // store out
        const int r = lane >> 2, c2 = 2 * (lane & 3);
        const int l0 = lt * 16 + r;
        float z0 = sZ[l0], z1 = sZ[l0 + 8];
        size_t ob = ((size_t)(b * L + lbase + l0) * H + hd) * 64;
#pragma unroll
        for (int n = 0; n < 4; n++) {
            int e = eh * 32 + n * 8 + c2;
            *(float2*)(out + ob + e) = make_float2(oacc[n][0] * z0, oacc[n][1] * z0);
            *(float2*)(out + ob + 8 * 1024 + e) = make_float2(oacc[n][2] * z1, oacc[n][3] * z1);
        }
    }
}

extern "C" void kernel_launch(void* const* d_in, const int* in_sizes, int n_in,
                              void* d_out, int out_size) {
    const float* q = (const float*)d_in[0];
    const float* k = (const float*)d_in[1];
    const float* v = (const float*)d_in[2];
    const float* P = (const float*)d_in[3];
    float* out = (float*)d_out;

    cudaFuncSetAttribute(kv_kernel, cudaFuncAttributeMaxDynamicSharedMemorySize, SMEM_A);
    cudaFuncSetAttribute(out_kernel, cudaFuncAttributeMaxDynamicSharedMemorySize, SMEM_B);

    kv_kernel<<<dim3(BH, NCHUNK), 512, SMEM_A>>>(k, v, P);
    reduce_kernel<<<(BH * M * E + 255) / 256, 256>>>();
    out_kernel<<<dim3(BH, NCHUNK), 512, SMEM_B>>>(q, P, out);
}

// round 4
// speedup vs baseline: 4.5585x; 1.3515x over previous
#include <cuda_runtime.h>
#include <cuda_fp16.h>
#include <cstdint>

constexpr int B = 4, L = 4096, H = 16, D = 64, M = 256, E = 64;
constexpr int BH = 64;
constexpr int NCHUNK = 16;
constexpr int TILES = 2;
constexpr float SCALE = 0.35355339059327378f;  // 64^-0.25
constexpr float KEPS = 1e-3f;
constexpr float ZEPS = 1e-6f;

// ---- global scratch ----
__device__ float g_KVpart[(size_t)NCHUNK * BH * M * E];
__device__ float g_Kspart[(size_t)NCHUNK * BH * M];
__device__ __align__(16) __half g_KVh[(size_t)BH * M * E];
__device__ float g_Ksum[(size_t)BH * M];

// ---- smem byte offsets (kernel A) ----
constexpr int A_PH = 0, A_SX = 32768, A_SV = 65536, A_XH = 98304, A_XL = 114688,
              A_VH = 131072, A_FH = 147456, A_FL = 180224, A_KS = 212992;
constexpr int SMEM_A = 221184;
// ---- smem byte offsets (kernel B) ----
constexpr int B_PH = 0, B_SX = 32768, B_XH = 65536, B_XL = 81920, B_FH = 98304,
              B_FL = 131072, B_KVH = 163840, B_KS = 196608, B_ZP = 197632, B_SZ = 198656;
constexpr int SMEM_B = 199168;

// ============================ low-level helpers ============================
__device__ __forceinline__ uint32_t smem_u32(const void* p) {
    uint32_t a;
    asm("{ .reg .u64 t; cvta.to.shared.u64 t, %1; cvt.u32.u64 %0, t; }" : "=r"(a) : "l"(p));
    return a;
}
__device__ __forceinline__ void ldsm_x4(uint32_t a, uint32_t r[4]) {
    asm volatile("ldmatrix.sync.aligned.m8n8.x4.shared.b16 {%0,%1,%2,%3}, [%4];"
                 : "=r"(r[0]), "=r"(r[1]), "=r"(r[2]), "=r"(r[3]) : "r"(a));
}
__device__ __forceinline__ void ldsm_x4t(uint32_t a, uint32_t r[4]) {
    asm volatile("ldmatrix.sync.aligned.m8n8.x4.trans.shared.b16 {%0,%1,%2,%3}, [%4];"
                 : "=r"(r[0]), "=r"(r[1]), "=r"(r[2]), "=r"(r[3]) : "r"(a));
}
__device__ __forceinline__ void ldsm_x2(uint32_t a, uint32_t r[2]) {
    asm volatile("ldmatrix.sync.aligned.m8n8.x2.shared.b16 {%0,%1}, [%2];"
                 : "=r"(r[0]), "=r"(r[1]) : "r"(a));
}
__device__ __forceinline__ void ldsm_x2t(uint32_t a, uint32_t r[2]) {
    asm volatile("ldmatrix.sync.aligned.m8n8.x2.trans.shared.b16 {%0,%1}, [%2];"
                 : "=r"(r[0]), "=r"(r[1]) : "r"(a));
}
__device__ __forceinline__ void mma16816(float c[4], const uint32_t a[4], const uint32_t b[2]) {
    asm volatile(
        "mma.sync.aligned.m16n8k16.row.col.f32.f16.f16.f32 "
        "{%0,%1,%2,%3}, {%4,%5,%6,%7}, {%8,%9}, {%0,%1,%2,%3};"
        : "+f"(c[0]), "+f"(c[1]), "+f"(c[2]), "+f"(c[3])
        : "r"(a[0]), "r"(a[1]), "r"(a[2]), "r"(a[3]), "r"(b[0]), "r"(b[1]));
}
__device__ __forceinline__ void cp_async16(uint32_t dst, const void* src) {
    asm volatile("cp.async.cg.shared.global [%0], [%1], 16;" ::"r"(dst), "l"(src));
}
#define CP_COMMIT() asm volatile("cp.async.commit_group;" ::: "memory")
#define CP_WAIT0() asm volatile("cp.async.wait_group 0;" ::: "memory")

__device__ __forceinline__ uint32_t packh2(float x, float y) {
    __half2 h = __floats2half2_rn(x, y);
    return *(uint32_t*)&h;
}
__device__ __forceinline__ void split_store8(float4 a, float4 b, char* hp, char* lp) {
    float x[8] = {a.x, a.y, a.z, a.w, b.x, b.y, b.z, b.w};
    uint32_t h[4], l[4];
#pragma unroll
    for (int i = 0; i < 4; i++) {
        __half h0 = __float2half_rn(x[2 * i]), h1 = __float2half_rn(x[2 * i + 1]);
        h[i] = packh2(__half2float(h0), __half2float(h1));
        l[i] = packh2(x[2 * i] - __half2float(h0), x[2 * i + 1] - __half2float(h1));
    }
    *(uint4*)hp = make_uint4(h[0], h[1], h[2], h[3]);
    *(uint4*)lp = make_uint4(l[0], l[1], l[2], l[3]);
}
__device__ __forceinline__ uint32_t adr128(uint32_t base, int row, int chunk) {
    return base + row * 128 + ((chunk ^ (row & 7)) << 4);
}
__device__ __forceinline__ uint32_t adr256(uint32_t base, int row, int chunk) {
    return base + row * 256 + ((chunk ^ (row & 7)) << 4);
}

// load P (scaled), fp16-hi only, SW layout [256 rows x 128B]
__device__ __forceinline__ void load_P(const float* __restrict__ P, char* smem, int PHo,
                                       int tid) {
    for (int u = tid; u < 2048; u += 512) {
        int m = u >> 3, ch = u & 7;
        float4 p0 = *(const float4*)(P + m * 64 + ch * 8);
        float4 p1 = *(const float4*)(P + m * 64 + ch * 8 + 4);
        p0.x *= SCALE; p0.y *= SCALE; p0.z *= SCALE; p0.w *= SCALE;
        p1.x *= SCALE; p1.y *= SCALE; p1.z *= SCALE; p1.w *= SCALE;
        uint4 hv;
        hv.x = packh2(p0.x, p0.y); hv.y = packh2(p0.z, p0.w);
        hv.z = packh2(p1.x, p1.y); hv.w = packh2(p1.z, p1.w);
        *(uint4*)(smem + PHo + adr128(0, m, ch)) = hv;
    }
}

// phi 2-term: acc += (Xh + Xl) @ Ph^T  for this warp's (lg, quad, hf) block
__device__ __forceinline__ void phi2(uint32_t sb, int XHo, int XLo, int PHo, float acc[8][4],
                                     int lg, int quad, int hf, int lane) {
    const int ln = lane & 7, g = lane >> 3, gB = g & 1;
    const int rowA = lg * 16 + ln + (g & 1) * 8;
    const int rowB = hf * 128 + quad * 64 + ln;
#pragma unroll
    for (int kk = 0; kk < 4; kk++) {
        uint32_t ah[4], al[4];
        int cA = (2 * kk + (g >> 1)) ^ ln;
        ldsm_x4(sb + XHo + rowA * 128 + (cA << 4), ah);
        ldsm_x4(sb + XLo + rowA * 128 + (cA << 4), al);
        int cB = (2 * kk + gB) ^ ln;
        uint32_t pb = sb + PHo + rowB * 128 + (cB << 4);
#pragma unroll
        for (int j = 0; j < 8; j++) {
            uint32_t b2[2];
            ldsm_x2(pb + j * 1024, b2);
            mma16816(acc[j], ah, b2);
            mma16816(acc[j], al, b2);
        }
    }
}

// ============================ Kernel A: KV + Ksum partials ============================
__global__ __launch_bounds__(512, 1) void kv_kernel(const float* __restrict__ k,
                                                    const float* __restrict__ v,
                                                    const float* __restrict__ P) {
    extern __shared__ char smem[];
    const uint32_t sb = smem_u32(smem);
    const int tid = threadIdx.x, w = tid >> 5, lane = tid & 31;
    const int ln = lane & 7, g = lane >> 3, gB = g & 1;
    const int bh = blockIdx.x, b = bh >> 4, hd = bh & 15;
    const int chunk = blockIdx.y;
    const int lg = w & 7, quad = w >> 3;  // phi roles
    const int mt = w & 7, eh = w >> 3;    // KV roles

    // prologue: stage tile 0 via cp.async
    {
        const size_t gbase = ((size_t)(b * L + chunk * 256) * H + hd) * 64;
#pragma unroll
        for (int i = 0; i < 4; i++) {
            int c = tid + i * 512;
            size_t off = gbase + (size_t)(c >> 4) * 1024 + (c & 15) * 4;
            cp_async16(sb + A_SX + c * 16, k + off);
            cp_async16(sb + A_SV + c * 16, v + off);
        }
        CP_COMMIT();
    }
    load_P(P, smem, A_PH, tid);
    for (int u = tid; u < 2048; u += 512) ((float*)(smem + A_KS))[u] = 0.f;

    float kvacc[2][4][4];
#pragma unroll
    for (int a = 0; a < 2; a++)
#pragma unroll
        for (int n = 0; n < 4; n++)
#pragma unroll
            for (int i = 0; i < 4; i++) kvacc[a][n][i] = 0.f;

    for (int t = 0; t < TILES; t++) {
        CP_WAIT0();
        __syncthreads();
        // convert staged fp32 -> fp16 split (X) and fp16 (V)
        for (int u = tid; u < 1024; u += 512) {
            int l = u >> 3, ch = u & 7;
            const float* px = (const float*)(smem + A_SX) + l * 64 + ch * 8;
            float4 x0 = *(const float4*)px, x1 = *(const float4*)(px + 4);
            uint32_t off = adr128(0, l, ch);
            split_store8(x0, x1, smem + A_XH + off, smem + A_XL + off);
            const float* pv = (const float*)(smem + A_SV) + l * 64 + ch * 8;
            float4 v0 = *(const float4*)pv, v1 = *(const float4*)(pv + 4);
            uint4 hv;
            hv.x = packh2(v0.x, v0.y); hv.y = packh2(v0.z, v0.w);
            hv.z = packh2(v1.x, v1.y); hv.w = packh2(v1.z, v1.w);
            *(uint4*)(smem + A_VH + off) = hv;
        }
        __syncthreads();
        if (t + 1 < TILES) {  // prefetch next tile during MMA phases
            const size_t gbase = ((size_t)(b * L + chunk * 256 + (t + 1) * 128) * H + hd) * 64;
#pragma unroll
            for (int i = 0; i < 4; i++) {
                int c = tid + i * 512;
                size_t off = gbase + (size_t)(c >> 4) * 1024 + (c & 15) * 4;
                cp_async16(sb + A_SX + c * 16, k + off);
                cp_async16(sb + A_SV + c * 16, v + off);
            }
            CP_COMMIT();
        }
#pragma unroll
        for (int hf = 0; hf < 2; hf++) {
            float acc[8][4];
#pragma unroll
            for (int j = 0; j < 8; j++)
#pragma unroll
                for (int i = 0; i < 4; i++) acc[j][i] = 0.f;
            phi2(sb, A_XH, A_XL, A_PH, acc, lg, quad, hf, lane);
            __syncthreads();  // prior F consumers done
            // relu+eps, store F hi/lo, Ksum partials
            const int r0 = lg * 16 + (lane >> 2);
            float* sKs = (float*)(smem + A_KS);
#pragma unroll
            for (int j = 0; j < 8; j++) {
                int ml = quad * 64 + j * 8 + 2 * (lane & 3);
                float f0 = fmaxf(acc[j][0], 0.f) + KEPS;
                float f1 = fmaxf(acc[j][1], 0.f) + KEPS;
                float f2 = fmaxf(acc[j][2], 0.f) + KEPS;
                float f3 = fmaxf(acc[j][3], 0.f) + KEPS;
                uint32_t o0 = adr256(0, r0, ml >> 3) + (ml & 7) * 2;
                uint32_t o1 = adr256(0, r0 + 8, ml >> 3) + (ml & 7) * 2;
                __half h0 = __float2half_rn(f0), h1 = __float2half_rn(f1);
                __half h2 = __float2half_rn(f2), h3 = __float2half_rn(f3);
                *(uint32_t*)(smem + A_FH + o0) = packh2(__half2float(h0), __half2float(h1));
                *(uint32_t*)(smem + A_FL + o0) =
                    packh2(f0 - __half2float(h0), f1 - __half2float(h1));
                *(uint32_t*)(smem + A_FH + o1) = packh2(__half2float(h2), __half2float(h3));
                *(uint32_t*)(smem + A_FL + o1) =
                    packh2(f2 - __half2float(h2), f3 - __half2float(h3));
                float s0 = f0 + f2, s1 = f1 + f3;
#pragma unroll
                for (int ox = 4; ox <= 16; ox <<= 1) {
                    s0 += __shfl_xor_sync(0xffffffffu, s0, ox);
                    s1 += __shfl_xor_sync(0xffffffffu, s1, ox);
                }
                if (lane < 4) {
                    sKs[lg * 256 + hf * 128 + ml] += s0;
                    sKs[lg * 256 + hf * 128 + ml + 1] += s1;
                }
            }
            __syncthreads();
            // KV mma: kvacc[hf][n] += F^T @ V  (F exact hi/lo, V fp16-hi)
#pragma unroll
            for (int kk = 0; kk < 8; kk++) {
                uint32_t fh[4], fl[4];
                int rowAt = kk * 16 + (g >> 1) * 8 + ln;
                int cAt = (2 * mt + (g & 1)) ^ ln;
                ldsm_x4t(sb + A_FH + rowAt * 256 + (cAt << 4), fh);
                ldsm_x4t(sb + A_FL + rowAt * 256 + (cAt << 4), fl);
                int rowBt = kk * 16 + gB * 8 + ln;
#pragma unroll
                for (int n = 0; n < 4; n++) {
                    uint32_t bv[2];
                    int cBt = (eh * 4 + n) ^ ln;
                    ldsm_x2t(sb + A_VH + rowBt * 128 + (cBt << 4), bv);
                    mma16816(kvacc[hf][n], fh, bv);
                    mma16816(kvacc[hf][n], fl, bv);
                }
            }
        }
    }
    // epilogue
    float* dst = g_KVpart + (size_t)(chunk * BH + bh) * M * E;
    const int r = lane >> 2, c2 = 2 * (lane & 3);
#pragma unroll
    for (int hf = 0; hf < 2; hf++)
#pragma unroll
        for (int n = 0; n < 4; n++) {
            int m0 = hf * 128 + mt * 16 + r;
            int e = eh * 32 + n * 8 + c2;
            *(float2*)(dst + m0 * 64 + e) = make_float2(kvacc[hf][n][0], kvacc[hf][n][1]);
            *(float2*)(dst + (m0 + 8) * 64 + e) = make_float2(kvacc[hf][n][2], kvacc[hf][n][3]);
        }
    __syncthreads();
    if (tid < 256) {
        const float* sKs = (const float*)(smem + A_KS);
        float s = 0.f;
#pragma unroll
        for (int i = 0; i < 8; i++) s += sKs[i * 256 + tid];
        g_Kspart[(size_t)(chunk * BH + bh) * M + tid] = s;
    }
}

// ============================ reduce: fp32 partials -> KVh fp16 + Ksum ============================
__global__ void reduce_kernel() {
    int idx = blockIdx.x * 256 + threadIdx.x;
    if (idx < BH * M * E) {
        float s = 0.f;
#pragma unroll
        for (int c = 0; c < NCHUNK; c++) s += g_KVpart[(size_t)c * BH * M * E + idx];
        g_KVh[idx] = __float2half_rn(s);
    }
    if (idx < BH * M) {
        float s = ZEPS;
#pragma unroll
        for (int c = 0; c < NCHUNK; c++) s += g_Kspart[(size_t)c * BH * M + idx];
        g_Ksum[idx] = s;
    }
}

// ============================ Kernel B: out = (Qf @ KV) * Z ============================
__global__ __launch_bounds__(512, 1) void out_kernel(const float* __restrict__ q,
                                                     const float* __restrict__ P,
                                                     float* __restrict__ out) {
    extern __shared__ char smem[];
    const uint32_t sb = smem_u32(smem);
    const int tid = threadIdx.x, w = tid >> 5, lane = tid & 31;
    const int ln = lane & 7, g = lane >> 3, gB = g & 1;
    const int bh = blockIdx.x, b = bh >> 4, hd = bh & 15;
    const int lg = w & 7, quad = w >> 3;  // phi roles
    const int lt = w & 7, eh = w >> 3;    // out roles

    // prologue: KVh (full 256x64 fp16) + stage tile 0
    {
#pragma unroll
        for (int i = 0; i < 4; i++) {
            int c = tid + i * 512;  // 0..2047 16B chunks
            int m = c >> 3, ch = c & 7;
            cp_async16(sb + B_KVH + adr128(0, m, ch), g_KVh + (size_t)bh * 16384 + c * 8);
        }
        CP_COMMIT();
        const size_t gbase = ((size_t)(b * L + blockIdx.y * 256) * H + hd) * 64;
#pragma unroll
        for (int i = 0; i < 4; i++) {
            int c = tid + i * 512;
            size_t off = gbase + (size_t)(c >> 4) * 1024 + (c & 15) * 4;
            cp_async16(sb + B_SX + c * 16, q + off);
        }
        CP_COMMIT();
    }
    load_P(P, smem, B_PH, tid);
    if (tid < 256) ((float*)(smem + B_KS))[tid] = g_Ksum[(size_t)bh * M + tid];

    for (int t = 0; t < TILES; t++) {
        CP_WAIT0();
        __syncthreads();
        for (int u = tid; u < 1024; u += 512) {
            int l = u >> 3, ch = u & 7;
            const float* px = (const float*)(smem + B_SX) + l * 64 + ch * 8;
            float4 x0 = *(const float4*)px, x1 = *(const float4*)(px + 4);
            uint32_t off = adr128(0, l, ch);
            split_store8(x0, x1, smem + B_XH + off, smem + B_XL + off);
        }
        __syncthreads();
        if (t + 1 < TILES) {
            const size_t gbase =
                ((size_t)(b * L + blockIdx.y * 256 + (t + 1) * 128) * H + hd) * 64;
#pragma unroll
            for (int i = 0; i < 4; i++) {
                int c = tid + i * 512;
                size_t off = gbase + (size_t)(c >> 4) * 1024 + (c & 15) * 4;
                cp_async16(sb + B_SX + c * 16, q + off);
            }
            CP_COMMIT();
        }
        float oacc[4][4];
#pragma unroll
        for (int n = 0; n < 4; n++)
#pragma unroll
            for (int i = 0; i < 4; i++) oacc[n][i] = 0.f;
        float zp0 = 0.f, zp1 = 0.f;
        const float* sKsm = (const float*)(smem + B_KS);

#pragma unroll
        for (int hf = 0; hf < 2; hf++) {
            float acc[8][4];
#pragma unroll
            for (int j = 0; j < 8; j++)
#pragma unroll
                for (int i = 0; i < 4; i++) acc[j][i] = 0.f;
            phi2(sb, B_XH, B_XL, B_PH, acc, lg, quad, hf, lane);
            __syncthreads();
            const int r0 = lg * 16 + (lane >> 2);
#pragma unroll
            for (int j = 0; j < 8; j++) {
                int ml = quad * 64 + j * 8 + 2 * (lane & 3);
                float f0 = fmaxf(acc[j][0], 0.f) + KEPS;
                float f1 = fmaxf(acc[j][1], 0.f) + KEPS;
                float f2 = fmaxf(acc[j][2], 0.f) + KEPS;
                float f3 = fmaxf(acc[j][3], 0.f) + KEPS;
                uint32_t o0 = adr256(0, r0, ml >> 3) + (ml & 7) * 2;
                uint32_t o1 = adr256(0, r0 + 8, ml >> 3) + (ml & 7) * 2;
                __half h0 = __float2half_rn(f0), h1 = __float2half_rn(f1);
                __half h2 = __float2half_rn(f2), h3 = __float2half_rn(f3);
                *(uint32_t*)(smem + B_FH + o0) = packh2(__half2float(h0), __half2float(h1));
                *(uint32_t*)(smem + B_FL + o0) =
                    packh2(f0 - __half2float(h0), f1 - __half2float(h1));
                *(uint32_t*)(smem + B_FH + o1) = packh2(__half2float(h2), __half2float(h3));
                *(uint32_t*)(smem + B_FL + o1) =
                    packh2(f2 - __half2float(h2), f3 - __half2float(h3));
                float ks0 = sKsm[hf * 128 + ml], ks1 = sKsm[hf * 128 + ml + 1];
                zp0 += f0 * ks0 + f1 * ks1;
                zp1 += f2 * ks0 + f3 * ks1;
            }
            __syncthreads();
            // out mma partial over this hf's 128 m-columns (Qf hi/lo x KVh)
#pragma unroll
            for (int kk = 0; kk < 8; kk++) {
                uint32_t qh[4], ql[4];
                int rowA = lt * 16 + ln + (g & 1) * 8;
                int cA = (2 * kk + (g >> 1)) ^ ln;
                ldsm_x4(sb + B_FH + rowA * 256 + (cA << 4), qh);
                ldsm_x4(sb + B_FL + rowA * 256 + (cA << 4), ql);
                int rowB = hf * 128 + kk * 16 + gB * 8 + ln;
#pragma unroll
                for (int n = 0; n < 4; n++) {
                    uint32_t bkv[2];
                    int cB = (eh * 4 + n) ^ ln;
                    ldsm_x2t(sb + B_KVH + rowB * 128 + (cB << 4), bkv);
                    mma16816(oacc[n], qh, bkv);
                    mma16816(oacc[n], ql, bkv);
                }
            }
        }
        // Z reduce
        zp0 += __shfl_xor_sync(0xffffffffu, zp0, 1);
        zp0 += __shfl_xor_sync(0xffffffffu, zp0, 2);
        zp1 += __shfl_xor_sync(0xffffffffu, zp1, 1);
        zp1 += __shfl_xor_sync(0xffffffffu, zp1, 2);
        float* sZp = (float*)(smem + B_ZP);
        if ((lane & 3) == 0) {
            sZp[quad * 128 + lg * 16 + (lane >> 2)] = zp0;
            sZp[quad * 128 + lg * 16 + (lane >> 2) + 8] = zp1;
        }
        __syncthreads();
        float* sZ = (float*)(smem + B_SZ);
        if (tid < 128) sZ[tid] = 1.0f / (sZp[tid] + sZp[128 + tid]);
        __syncthreads();
        // store
        const int r = lane >> 2, c2 = 2 * (lane & 3);
        const int l0 = lt * 16 + r;
        float z0 = sZ[l0], z1 = sZ[l0 + 8];
        size_t ob = ((size_t)(b * L + blockIdx.y * 256 + t * 128 + l0) * H + hd) * 64;
#pragma unroll
        for (int n = 0; n < 4; n++) {
            int e = eh * 32 + n * 8 + c2;
            *(float2*)(out + ob + e) = make_float2(oacc[n][0] * z0, oacc[n][1] * z0);
            *(float2*)(out + ob + 8 * 1024 + e) = make_float2(oacc[n][2] * z1, oacc[n][3] * z1);
        }
    }
}

extern "C" void kernel_launch(void* const* d_in, const int* in_sizes, int n_in,
                              void* d_out, int out_size) {
    const float* q = (const float*)d_in[0];
    const float* k = (const float*)d_in[1];
    const float* v = (const float*)d_in[2];
    const float* P = (const float*)d_in[3];
    float* out = (float*)d_out;

    cudaFuncSetAttribute(kv_kernel, cudaFuncAttributeMaxDynamicSharedMemorySize, SMEM_A);
    cudaFuncSetAttribute(out_kernel, cudaFuncAttributeMaxDynamicSharedMemorySize, SMEM_B);

    kv_kernel<<<dim3(BH, NCHUNK), 512, SMEM_A>>>(k, v, P);
    reduce_kernel<<<(BH * M * E + 255) / 256, 256>>>();
    out_kernel<<<dim3(BH, NCHUNK), 512, SMEM_B>>>(q, P, out);
}

// round 6
// speedup vs baseline: 6.1509x; 1.3493x over previous
#include <cuda_runtime.h>
#include <cuda_fp16.h>
#include <cstdint>

constexpr int B = 4, L = 4096, H = 16, D = 64, M = 256, E = 64;
constexpr int BH = 64;
constexpr int NCHUNK = 16;
constexpr int TILES = 2;
constexpr float SCALE = 0.35355339059327378f;  // 64^-0.25
constexpr float KEPS = 1e-3f;
constexpr float ZEPS = 1e-6f;

// ---- global scratch ----
__device__ float g_KVpart[(size_t)NCHUNK * BH * M * E];
__device__ float g_Kspart[(size_t)NCHUNK * BH * M];
__device__ __align__(16) __half g_KVh[(size_t)BH * M * E];
__device__ float g_Ksum[(size_t)BH * M];

// ---- smem byte offsets (kernel A) ----
constexpr int A_PH = 0, A_SX = 32768, A_SV = 65536, A_XH = 98304, A_VH = 114688,
              A_FH = 131072, A_KS = 163840;
constexpr int SMEM_A = 172032;
// ---- smem byte offsets (kernel B) ----
constexpr int B_PH = 0, B_SX = 32768, B_XH = 65536, B_FH = 81920, B_KVH = 114688,
              B_KS = 147456, B_ZP = 148480, B_SZ = 149504;
constexpr int SMEM_B = 150016;

// ============================ low-level helpers ============================
__device__ __forceinline__ uint32_t smem_u32(const void* p) {
    uint32_t a;
    asm("{ .reg .u64 t; cvta.to.shared.u64 t, %1; cvt.u32.u64 %0, t; }" : "=r"(a) : "l"(p));
    return a;
}
__device__ __forceinline__ void ldsm_x4(uint32_t a, uint32_t r[4]) {
    asm volatile("ldmatrix.sync.aligned.m8n8.x4.shared.b16 {%0,%1,%2,%3}, [%4];"
                 : "=r"(r[0]), "=r"(r[1]), "=r"(r[2]), "=r"(r[3]) : "r"(a));
}
__device__ __forceinline__ void ldsm_x4t(uint32_t a, uint32_t r[4]) {
    asm volatile("ldmatrix.sync.aligned.m8n8.x4.trans.shared.b16 {%0,%1,%2,%3}, [%4];"
                 : "=r"(r[0]), "=r"(r[1]), "=r"(r[2]), "=r"(r[3]) : "r"(a));
}
__device__ __forceinline__ void ldsm_x2(uint32_t a, uint32_t r[2]) {
    asm volatile("ldmatrix.sync.aligned.m8n8.x2.shared.b16 {%0,%1}, [%2];"
                 : "=r"(r[0]), "=r"(r[1]) : "r"(a));
}
__device__ __forceinline__ void ldsm_x2t(uint32_t a, uint32_t r[2]) {
    asm volatile("ldmatrix.sync.aligned.m8n8.x2.trans.shared.b16 {%0,%1}, [%2];"
                 : "=r"(r[0]), "=r"(r[1]) : "r"(a));
}
__device__ __forceinline__ void mma16816(float c[4], const uint32_t a[4], const uint32_t b[2]) {
    asm volatile(
        "mma.sync.aligned.m16n8k16.row.col.f32.f16.f16.f32 "
        "{%0,%1,%2,%3}, {%4,%5,%6,%7}, {%8,%9}, {%0,%1,%2,%3};"
        : "+f"(c[0]), "+f"(c[1]), "+f"(c[2]), "+f"(c[3])
        : "r"(a[0]), "r"(a[1]), "r"(a[2]), "r"(a[3]), "r"(b[0]), "r"(b[1]));
}
__device__ __forceinline__ void cp_async16(uint32_t dst, const void* src) {
    asm volatile("cp.async.cg.shared.global [%0], [%1], 16;" ::"r"(dst), "l"(src));
}
#define CP_COMMIT() asm volatile("cp.async.commit_group;" ::: "memory")
#define CP_WAIT0() asm volatile("cp.async.wait_group 0;" ::: "memory")

__device__ __forceinline__ uint32_t packh2(float x, float y) {
    __half2 h = __floats2half2_rn(x, y);
    return *(uint32_t*)&h;
}
// pack 8 fp32 -> 8 fp16 into one 16B smem store
__device__ __forceinline__ void pack_store8(float4 a, float4 b, char* hp) {
    uint4 hv;
    hv.x = packh2(a.x, a.y);
    hv.y = packh2(a.z, a.w);
    hv.z = packh2(b.x, b.y);
    hv.w = packh2(b.z, b.w);
    *(uint4*)hp = hv;
}
__device__ __forceinline__ uint32_t adr128(uint32_t base, int row, int chunk) {
    return base + row * 128 + ((chunk ^ (row & 7)) << 4);
}
__device__ __forceinline__ uint32_t adr256(uint32_t base, int row, int chunk) {
    return base + row * 256 + ((chunk ^ (row & 7)) << 4);
}

// load P (scaled), fp16, SW layout [256 rows x 128B]
__device__ __forceinline__ void load_P(const float* __restrict__ P, char* smem, int PHo,
                                       int tid) {
    for (int u = tid; u < 2048; u += 512) {
        int m = u >> 3, ch = u & 7;
        float4 p0 = *(const float4*)(P + m * 64 + ch * 8);
        float4 p1 = *(const float4*)(P + m * 64 + ch * 8 + 4);
        p0.x *= SCALE; p0.y *= SCALE; p0.z *= SCALE; p0.w *= SCALE;
        p1.x *= SCALE; p1.y *= SCALE; p1.z *= SCALE; p1.w *= SCALE;
        pack_store8(p0, p1, smem + PHo + adr128(0, m, ch));
    }
}

// phi single-term: acc += Xh @ Ph^T  for this warp's (lg, quad, hf) block
__device__ __forceinline__ void phi1(uint32_t sb, int XHo, int PHo, float acc[8][4], int lg,
                                     int quad, int hf, int lane) {
    const int ln = lane & 7, g = lane >> 3, gB = g & 1;
    const int rowA = lg * 16 + ln + (g & 1) * 8;
    const int rowB = hf * 128 + quad * 64 + ln;
#pragma unroll
    for (int kk = 0; kk < 4; kk++) {
        uint32_t ah[4];
        int cA = (2 * kk + (g >> 1)) ^ ln;
        ldsm_x4(sb + XHo + rowA * 128 + (cA << 4), ah);
        int cB = (2 * kk + gB) ^ ln;
        uint32_t pb = sb + PHo + rowB * 128 + (cB << 4);
#pragma unroll
        for (int j = 0; j < 8; j++) {
            uint32_t b2[2];
            ldsm_x2(pb + j * 1024, b2);
            mma16816(acc[j], ah, b2);
        }
    }
}

// ============================ Kernel A: KV + Ksum partials ============================
__global__ __launch_bounds__(512, 1) void kv_kernel(const float* __restrict__ k,
                                                    const float* __restrict__ v,
                                                    const float* __restrict__ P) {
    extern __shared__ char smem[];
    const uint32_t sb = smem_u32(smem);
    const int tid = threadIdx.x, w = tid >> 5, lane = tid & 31;
    const int ln = lane & 7, g = lane >> 3, gB = g & 1;
    const int bh = blockIdx.x, b = bh >> 4, hd = bh & 15;
    const int chunk = blockIdx.y;
    const int lg = w & 7, quad = w >> 3;  // phi roles
    const int mt = w & 7, eh = w >> 3;    // KV roles

    // prologue: stage tile 0 via cp.async
    {
        const size_t gbase = ((size_t)(b * L + chunk * 256) * H + hd) * 64;
#pragma unroll
        for (int i = 0; i < 4; i++) {
            int c = tid + i * 512;
            size_t off = gbase + (size_t)(c >> 4) * 1024 + (c & 15) * 4;
            cp_async16(sb + A_SX + c * 16, k + off);
            cp_async16(sb + A_SV + c * 16, v + off);
        }
        CP_COMMIT();
    }
    load_P(P, smem, A_PH, tid);
    for (int u = tid; u < 2048; u += 512) ((float*)(smem + A_KS))[u] = 0.f;

    float kvacc[2][4][4];
#pragma unroll
    for (int a = 0; a < 2; a++)
#pragma unroll
        for (int n = 0; n < 4; n++)
#pragma unroll
            for (int i = 0; i < 4; i++) kvacc[a][n][i] = 0.f;

    for (int t = 0; t < TILES; t++) {
        CP_WAIT0();
        __syncthreads();
        // convert staged fp32 -> fp16 (X and V)
        for (int u = tid; u < 1024; u += 512) {
            int l = u >> 3, ch = u & 7;
            const float* px = (const float*)(smem + A_SX) + l * 64 + ch * 8;
            float4 x0 = *(const float4*)px, x1 = *(const float4*)(px + 4);
            uint32_t off = adr128(0, l, ch);
            pack_store8(x0, x1, smem + A_XH + off);
            const float* pv = (const float*)(smem + A_SV) + l * 64 + ch * 8;
            float4 v0 = *(const float4*)pv, v1 = *(const float4*)(pv + 4);
            pack_store8(v0, v1, smem + A_VH + off);
        }
        __syncthreads();
        if (t + 1 < TILES) {  // prefetch next tile during MMA phases
            const size_t gbase = ((size_t)(b * L + chunk * 256 + (t + 1) * 128) * H + hd) * 64;
#pragma unroll
            for (int i = 0; i < 4; i++) {
                int c = tid + i * 512;
                size_t off = gbase + (size_t)(c >> 4) * 1024 + (c & 15) * 4;
                cp_async16(sb + A_SX + c * 16, k + off);
                cp_async16(sb + A_SV + c * 16, v + off);
            }
            CP_COMMIT();
        }
#pragma unroll
        for (int hf = 0; hf < 2; hf++) {
            float acc[8][4];
#pragma unroll
            for (int j = 0; j < 8; j++)
#pragma unroll
                for (int i = 0; i < 4; i++) acc[j][i] = 0.f;
            phi1(sb, A_XH, A_PH, acc, lg, quad, hf, lane);
            __syncthreads();  // prior F consumers done
            // relu+eps, store F (fp16), Ksum partials (exact fp32)
            const int r0 = lg * 16 + (lane >> 2);
            float* sKs = (float*)(smem + A_KS);
#pragma unroll
            for (int j = 0; j < 8; j++) {
                int ml = quad * 64 + j * 8 + 2 * (lane & 3);
                float f0 = fmaxf(acc[j][0], 0.f) + KEPS;
                float f1 = fmaxf(acc[j][1], 0.f) + KEPS;
                float f2 = fmaxf(acc[j][2], 0.f) + KEPS;
                float f3 = fmaxf(acc[j][3], 0.f) + KEPS;
                uint32_t o0 = adr256(0, r0, ml >> 3) + (ml & 7) * 2;
                uint32_t o1 = adr256(0, r0 + 8, ml >> 3) + (ml & 7) * 2;
                *(uint32_t*)(smem + A_FH + o0) = packh2(f0, f1);
                *(uint32_t*)(smem + A_FH + o1) = packh2(f2, f3);
                float s0 = f0 + f2, s1 = f1 + f3;
#pragma unroll
                for (int ox = 4; ox <= 16; ox <<= 1) {
                    s0 += __shfl_xor_sync(0xffffffffu, s0, ox);
                    s1 += __shfl_xor_sync(0xffffffffu, s1, ox);
                }
                if (lane < 4) {
                    sKs[lg * 256 + hf * 128 + ml] += s0;
                    sKs[lg * 256 + hf * 128 + ml + 1] += s1;
                }
            }
            __syncthreads();
            // KV mma: kvacc[hf][n] += F^T @ V  (single term)
#pragma unroll
            for (int kk = 0; kk < 8; kk++) {
                uint32_t fh[4];
                int rowAt = kk * 16 + (g >> 1) * 8 + ln;
                int cAt = (2 * mt + (g & 1)) ^ ln;
                ldsm_x4t(sb + A_FH + rowAt * 256 + (cAt << 4), fh);
                int rowBt = kk * 16 + gB * 8 + ln;
#pragma unroll
                for (int n = 0; n < 4; n++) {
                    uint32_t bv[2];
                    int cBt = (eh * 4 + n) ^ ln;
                    ldsm_x2t(sb + A_VH + rowBt * 128 + (cBt << 4), bv);
                    mma16816(kvacc[hf][n], fh, bv);
                }
            }
        }
    }
    // epilogue
    float* dst = g_KVpart + (size_t)(chunk * BH + bh) * M * E;
    const int r = lane >> 2, c2 = 2 * (lane & 3);
#pragma unroll
    for (int hf = 0; hf < 2; hf++)
#pragma unroll
        for (int n = 0; n < 4; n++) {
            int m0 = hf * 128 + mt * 16 + r;
            int e = eh * 32 + n * 8 + c2;
            *(float2*)(dst + m0 * 64 + e) = make_float2(kvacc[hf][n][0], kvacc[hf][n][1]);
            *(float2*)(dst + (m0 + 8) * 64 + e) = make_float2(kvacc[hf][n][2], kvacc[hf][n][3]);
        }
    __syncthreads();
    if (tid < 256) {
        const float* sKs = (const float*)(smem + A_KS);
        float s = 0.f;
#pragma unroll
        for (int i = 0; i < 8; i++) s += sKs[i * 256 + tid];
        g_Kspart[(size_t)(chunk * BH + bh) * M + tid] = s;
    }
}

// ============================ reduce: fp32 partials -> KVh fp16 + Ksum ============================
__global__ void reduce_kernel() {
    int idx = blockIdx.x * 256 + threadIdx.x;
    if (idx < BH * M * E) {
        float s = 0.f;
#pragma unroll
        for (int c = 0; c < NCHUNK; c++) s += g_KVpart[(size_t)c * BH * M * E + idx];
        g_KVh[idx] = __float2half_rn(s);
    }
    if (idx < BH * M) {
        float s = ZEPS;
#pragma unroll
        for (int c = 0; c < NCHUNK; c++) s += g_Kspart[(size_t)c * BH * M + idx];
        g_Ksum[idx] = s;
    }
}

// ============================ Kernel B: out = (Qf @ KV) * Z ============================
__global__ __launch_bounds__(512, 1) void out_kernel(const float* __restrict__ q,
                                                     const float* __restrict__ P,
                                                     float* __restrict__ out) {
    extern __shared__ char smem[];
    const uint32_t sb = smem_u32(smem);
    const int tid = threadIdx.x, w = tid >> 5, lane = tid & 31;
    const int ln = lane & 7, g = lane >> 3, gB = g & 1;
    const int bh = blockIdx.x, b = bh >> 4, hd = bh & 15;
    const int lg = w & 7, quad = w >> 3;  // phi roles
    const int lt = w & 7, eh = w >> 3;    // out roles

    // prologue: KVh (full 256x64 fp16) + stage tile 0
    {
#pragma unroll
        for (int i = 0; i < 4; i++) {
            int c = tid + i * 512;  // 0..2047 16B chunks
            int m = c >> 3, ch = c & 7;
            cp_async16(sb + B_KVH + adr128(0, m, ch), g_KVh + (size_t)bh * 16384 + c * 8);
        }
        CP_COMMIT();
        const size_t gbase = ((size_t)(b * L + blockIdx.y * 256) * H + hd) * 64;
#pragma unroll
        for (int i = 0; i < 4; i++) {
            int c = tid + i * 512;
            size_t off = gbase + (size_t)(c >> 4) * 1024 + (c & 15) * 4;
            cp_async16(sb + B_SX + c * 16, q + off);
        }
        CP_COMMIT();
    }
    load_P(P, smem, B_PH, tid);
    if (tid < 256) ((float*)(smem + B_KS))[tid] = g_Ksum[(size_t)bh * M + tid];

    for (int t = 0; t < TILES; t++) {
        CP_WAIT0();
        __syncthreads();
        for (int u = tid; u < 1024; u += 512) {
            int l = u >> 3, ch = u & 7;
            const float* px = (const float*)(smem + B_SX) + l * 64 + ch * 8;
            float4 x0 = *(const float4*)px, x1 = *(const float4*)(px + 4);
            pack_store8(x0, x1, smem + B_XH + adr128(0, l, ch));
        }
        __syncthreads();
        if (t + 1 < TILES) {
            const size_t gbase =
                ((size_t)(b * L + blockIdx.y * 256 + (t + 1) * 128) * H + hd) * 64;
#pragma unroll
            for (int i = 0; i < 4; i++) {
                int c = tid + i * 512;
                size_t off = gbase + (size_t)(c >> 4) * 1024 + (c & 15) * 4;
                cp_async16(sb + B_SX + c * 16, q + off);
            }
            CP_COMMIT();
        }
        float oacc[4][4];
#pragma unroll
        for (int n = 0; n < 4; n++)
#pragma unroll
            for (int i = 0; i < 4; i++) oacc[n][i] = 0.f;
        float zp0 = 0.f, zp1 = 0.f;
        const float* sKsm = (const float*)(smem + B_KS);

#pragma unroll
        for (int hf = 0; hf < 2; hf++) {
            float acc[8][4];
#pragma unroll
            for (int j = 0; j < 8; j++)
#pragma unroll
                for (int i = 0; i < 4; i++) acc[j][i] = 0.f;
            phi1(sb, B_XH, B_PH, acc, lg, quad, hf, lane);
            __syncthreads();
            const int r0 = lg * 16 + (lane >> 2);
#pragma unroll
            for (int j = 0; j < 8; j++) {
                int ml = quad * 64 + j * 8 + 2 * (lane & 3);
                float f0 = fmaxf(acc[j][0], 0.f) + KEPS;
                float f1 = fmaxf(acc[j][1], 0.f) + KEPS;
                float f2 = fmaxf(acc[j][2], 0.f) + KEPS;
                float f3 = fmaxf(acc[j][3], 0.f) + KEPS;
                uint32_t o0 = adr256(0, r0, ml >> 3) + (ml & 7) * 2;
                uint32_t o1 = adr256(0, r0 + 8, ml >> 3) + (ml & 7) * 2;
                *(uint32_t*)(smem + B_FH + o0) = packh2(f0, f1);
                *(uint32_t*)(smem + B_FH + o1) = packh2(f2, f3);
                float ks0 = sKsm[hf * 128 + ml], ks1 = sKsm[hf * 128 + ml + 1];
                zp0 += f0 * ks0 + f1 * ks1;
                zp1 += f2 * ks0 + f3 * ks1;
            }
            __syncthreads();
            // out mma partial over this hf's 128 m-columns (single term)
#pragma unroll
            for (int kk = 0; kk < 8; kk++) {
                uint32_t qh[4];
                int rowA = lt * 16 + ln + (g & 1) * 8;
                int cA = (2 * kk + (g >> 1)) ^ ln;
                ldsm_x4(sb + B_FH + rowA * 256 + (cA << 4), qh);
                int rowB = hf * 128 + kk * 16 + gB * 8 + ln;
#pragma unroll
                for (int n = 0; n < 4; n++) {
                    uint32_t bkv[2];
                    int cB = (eh * 4 + n) ^ ln;
                    ldsm_x2t(sb + B_KVH + rowB * 128 + (cB << 4), bkv);
                    mma16816(oacc[n], qh, bkv);
                }
            }
        }
        // Z reduce
        zp0 += __shfl_xor_sync(0xffffffffu, zp0, 1);
        zp0 += __shfl_xor_sync(0xffffffffu, zp0, 2);
        zp1 += __shfl_xor_sync(0xffffffffu, zp1, 1);
        zp1 += __shfl_xor_sync(0xffffffffu, zp1, 2);
        float* sZp = (float*)(smem + B_ZP);
        if ((lane & 3) == 0) {
            sZp[quad * 128 + lg * 16 + (lane >> 2)] = zp0;
            sZp[quad * 128 + lg * 16 + (lane >> 2) + 8] = zp1;
        }
        __syncthreads();
        float* sZ = (float*)(smem + B_SZ);
        if (tid < 128) sZ[tid] = 1.0f / (sZp[tid] + sZp[128 + tid]);
        __syncthreads();
        // store
        const int r = lane >> 2, c2 = 2 * (lane & 3);
        const int l0 = lt * 16 + r;
        float z0 = sZ[l0], z1 = sZ[l0 + 8];
        size_t ob = ((size_t)(b * L + blockIdx.y * 256 + t * 128 + l0) * H + hd) * 64;
#pragma unroll
        for (int n = 0; n < 4; n++) {
            int e = eh * 32 + n * 8 + c2;
            *(float2*)(out + ob + e) = make_float2(oacc[n][0] * z0, oacc[n][1] * z0);
            *(float2*)(out + ob + 8 * 1024 + e) = make_float2(oacc[n][2] * z1, oacc[n][3] * z1);
        }
    }
}

extern "C" void kernel_launch(void* const* d_in, const int* in_sizes, int n_in,
                              void* d_out, int out_size) {
    const float* q = (const float*)d_in[0];
    const float* k = (const float*)d_in[1];
    const float* v = (const float*)d_in[2];
    const float* P = (const float*)d_in[3];
    float* out = (float*)d_out;

    cudaFuncSetAttribute(kv_kernel, cudaFuncAttributeMaxDynamicSharedMemorySize, SMEM_A);
    cudaFuncSetAttribute(out_kernel, cudaFuncAttributeMaxDynamicSharedMemorySize, SMEM_B);

    kv_kernel<<<dim3(BH, NCHUNK), 512, SMEM_A>>>(k, v, P);
    reduce_kernel<<<(BH * M * E + 255) / 256, 256>>>();
    out_kernel<<<dim3(BH, NCHUNK), 512, SMEM_B>>>(q, P, out);
}

// round 7
// speedup vs baseline: 6.9102x; 1.1234x over previous
#include <cuda_runtime.h>
#include <cuda_fp16.h>
#include <cstdint>

constexpr int B = 4, L = 4096, H = 16, D = 64, M = 256, E = 64;
constexpr int BH = 64;
constexpr int NCHUNK = 8;
constexpr int TILES = 4;
constexpr float SCALE = 0.35355339059327378f;  // 64^-0.25
constexpr float KEPS = 1e-3f;
constexpr float ZEPS = 1e-6f;

// ---- global scratch ----
__device__ float g_KVpart[(size_t)NCHUNK * BH * M * E];
__device__ float g_Kspart[(size_t)NCHUNK * BH * M];
__device__ __align__(16) __half g_KVh[(size_t)BH * M * E];
__device__ float g_Ksum[(size_t)BH * M];

// ---- smem byte offsets (kernel A) ----
constexpr int A_PH = 0, A_SX = 32768, A_SV = 65536, A_XH = 98304, A_VH = 114688,
              A_F0 = 131072, A_F1 = 163840;
constexpr int SMEM_A = 196608;
// ---- smem byte offsets (kernel B) ----
constexpr int B_PH = 0, B_SX = 32768, B_XH = 65536, B_F0 = 81920, B_F1 = 114688,
              B_KVH = 147456, B_KS = 180224, B_ZP = 181248, B_SZ = 182272;
constexpr int SMEM_B = 182784;

// ============================ low-level helpers ============================
__device__ __forceinline__ uint32_t smem_u32(const void* p) {
    uint32_t a;
    asm("{ .reg .u64 t; cvta.to.shared.u64 t, %1; cvt.u32.u64 %0, t; }" : "=r"(a) : "l"(p));
    return a;
}
__device__ __forceinline__ void ldsm_x4(uint32_t a, uint32_t r[4]) {
    asm volatile("ldmatrix.sync.aligned.m8n8.x4.shared.b16 {%0,%1,%2,%3}, [%4];"
                 : "=r"(r[0]), "=r"(r[1]), "=r"(r[2]), "=r"(r[3]) : "r"(a));
}
__device__ __forceinline__ void ldsm_x4t(uint32_t a, uint32_t r[4]) {
    asm volatile("ldmatrix.sync.aligned.m8n8.x4.trans.shared.b16 {%0,%1,%2,%3}, [%4];"
                 : "=r"(r[0]), "=r"(r[1]), "=r"(r[2]), "=r"(r[3]) : "r"(a));
}
__device__ __forceinline__ void mma16816(float c[4], const uint32_t a[4], const uint32_t b[2]) {
    asm volatile(
        "mma.sync.aligned.m16n8k16.row.col.f32.f16.f16.f32 "
        "{%0,%1,%2,%3}, {%4,%5,%6,%7}, {%8,%9}, {%0,%1,%2,%3};"
        : "+f"(c[0]), "+f"(c[1]), "+f"(c[2]), "+f"(c[3])
        : "r"(a[0]), "r"(a[1]), "r"(a[2]), "r"(a[3]), "r"(b[0]), "r"(b[1]));
}
__device__ __forceinline__ void cp_async16(uint32_t dst, const void* src) {
    asm volatile("cp.async.cg.shared.global [%0], [%1], 16;" ::"r"(dst), "l"(src));
}
#define CP_COMMIT() asm volatile("cp.async.commit_group;" ::: "memory")
#define CP_WAIT0() asm volatile("cp.async.wait_group 0;" ::: "memory")

__device__ __forceinline__ uint32_t packh2(float x, float y) {
    __half2 h = __floats2half2_rn(x, y);
    return *(uint32_t*)&h;
}
__device__ __forceinline__ void pack_store8(float4 a, float4 b, char* hp) {
    uint4 hv;
    hv.x = packh2(a.x, a.y);
    hv.y = packh2(a.z, a.w);
    hv.z = packh2(b.x, b.y);
    hv.w = packh2(b.z, b.w);
    *(uint4*)hp = hv;
}
__device__ __forceinline__ uint32_t adr128(uint32_t base, int row, int chunk) {
    return base + row * 128 + ((chunk ^ (row & 7)) << 4);
}
__device__ __forceinline__ uint32_t adr256(uint32_t base, int row, int chunk) {
    return base + row * 256 + ((chunk ^ (row & 7)) << 4);
}

// load P (scaled), fp16, SW layout [256 rows x 128B]
__device__ __forceinline__ void load_P(const float* __restrict__ P, char* smem, int PHo,
                                       int tid) {
    for (int u = tid; u < 2048; u += 512) {
        int m = u >> 3, ch = u & 7;
        float4 p0 = *(const float4*)(P + m * 64 + ch * 8);
        float4 p1 = *(const float4*)(P + m * 64 + ch * 8 + 4);
        p0.x *= SCALE; p0.y *= SCALE; p0.z *= SCALE; p0.w *= SCALE;
        p1.x *= SCALE; p1.y *= SCALE; p1.z *= SCALE; p1.w *= SCALE;
        pack_store8(p0, p1, smem + PHo + adr128(0, m, ch));
    }
}

// phi: acc += X @ P^T for warp block (lg rows, quad cols, hf half); x4 B loads
__device__ __forceinline__ void phi_pass(uint32_t sb, int XHo, int PHo, float acc[8][4],
                                         int lg, int quad, int hf, int lane) {
    const int ln = lane & 7, g2 = lane >> 3;
    const int rowA = lg * 16 + ln + (g2 & 1) * 8;
    const int rowB = hf * 128 + quad * 64 + (g2 >> 1) * 8 + ln;
#pragma unroll
    for (int kk = 0; kk < 4; kk++) {
        uint32_t ah[4];
        int cA = (2 * kk + (g2 >> 1)) ^ ln;
        ldsm_x4(sb + XHo + rowA * 128 + (cA << 4), ah);
        int cB = (2 * kk + (g2 & 1)) ^ ln;
        uint32_t pb = sb + PHo + rowB * 128 + (cB << 4);
#pragma unroll
        for (int j2 = 0; j2 < 4; j2++) {
            uint32_t b4[4];
            ldsm_x4(pb + j2 * 2048, b4);
            mma16816(acc[2 * j2], ah, b4);
            mma16816(acc[2 * j2 + 1], ah, b4 + 2);
        }
    }
}

// relu+eps and pack F fragment to smem buffer Fo (adr256 layout)
__device__ __forceinline__ void store_F(char* smem, int Fo, const float acc[8][4], int lg,
                                        int quad, int lane) {
    const int r0 = lg * 16 + (lane >> 2);
#pragma unroll
    for (int j = 0; j < 8; j++) {
        int ml = quad * 64 + j * 8 + 2 * (lane & 3);
        float f0 = fmaxf(acc[j][0], 0.f) + KEPS;
        float f1 = fmaxf(acc[j][1], 0.f) + KEPS;
        float f2 = fmaxf(acc[j][2], 0.f) + KEPS;
        float f3 = fmaxf(acc[j][3], 0.f) + KEPS;
        *(uint32_t*)(smem + Fo + adr256(0, r0, ml >> 3) + (ml & 7) * 2) = packh2(f0, f1);
        *(uint32_t*)(smem + Fo + adr256(0, r0 + 8, ml >> 3) + (ml & 7) * 2) = packh2(f2, f3);
    }
}

// KV pass: kvacc += F^T @ V, ksacc += F^T @ ones; x4t B loads
__device__ __forceinline__ void kv_mma_pass(uint32_t sb, int Fo, int Vo, float kvacc[4][4],
                                            float ksacc[4], const uint32_t onesb[2], int mt,
                                            int eh, int lane) {
    const int ln = lane & 7, g2 = lane >> 3;
#pragma unroll
    for (int kk = 0; kk < 8; kk++) {
        uint32_t fh[4];
        int rowAt = kk * 16 + (g2 >> 1) * 8 + ln;
        int cAt = (2 * mt + (g2 & 1)) ^ ln;
        ldsm_x4t(sb + Fo + rowAt * 256 + (cAt << 4), fh);
        int rowBt = kk * 16 + (g2 & 1) * 8 + ln;
#pragma unroll
        for (int n2 = 0; n2 < 2; n2++) {
            uint32_t bv[4];
            int cBt = (eh * 4 + n2 * 2 + (g2 >> 1)) ^ ln;
            ldsm_x4t(sb + Vo + rowBt * 128 + (cBt << 4), bv);
            mma16816(kvacc[n2 * 2], fh, bv);
            mma16816(kvacc[n2 * 2 + 1], fh, bv + 2);
        }
        mma16816(ksacc, fh, onesb);
    }
}

// ============================ Kernel A: KV + Ksum partials ============================
__global__ __launch_bounds__(512, 1) void kv_kernel(const float* __restrict__ k,
                                                    const float* __restrict__ v,
                                                    const float* __restrict__ P) {
    extern __shared__ char smem[];
    const uint32_t sb = smem_u32(smem);
    const int tid = threadIdx.x, w = tid >> 5, lane = tid & 31;
    const int bh = blockIdx.x, b = bh >> 4, hd = bh & 15;
    const int chunk = blockIdx.y;
    const int lg = w & 7, quad = w >> 3;  // phi roles
    const int mt = w & 7, eh = w >> 3;    // KV roles
    const size_t cta_base = ((size_t)(b * L + chunk * (TILES * 128)) * H + hd) * 64;

    // stage tile 0
#pragma unroll
    for (int i = 0; i < 4; i++) {
        int c = tid + i * 512;
        size_t off = cta_base + (size_t)(c >> 4) * 1024 + (c & 15) * 4;
        cp_async16(sb + A_SX + c * 16, k + off);
        cp_async16(sb + A_SV + c * 16, v + off);
    }
    CP_COMMIT();
    load_P(P, smem, A_PH, tid);

    float kvacc[2][4][4];
    float ksacc[2][4];
#pragma unroll
    for (int a = 0; a < 2; a++) {
#pragma unroll
        for (int n = 0; n < 4; n++) {
            ksacc[a][n] = 0.f;
#pragma unroll
            for (int i = 0; i < 4; i++) kvacc[a][n][i] = 0.f;
        }
    }
    const uint32_t onesb[2] = {0x3C003C00u, 0x3C003C00u};

    for (int t = 0; t < TILES; t++) {
        CP_WAIT0();
        __syncthreads();  // staged data ready; prior KV1 done
        // convert staged fp32 -> fp16 (X, V)
        for (int u = tid; u < 1024; u += 512) {
            int l = u >> 3, ch = u & 7;
            const float* px = (const float*)(smem + A_SX) + l * 64 + ch * 8;
            pack_store8(*(const float4*)px, *(const float4*)(px + 4),
                        smem + A_XH + adr128(0, l, ch));
            const float* pv = (const float*)(smem + A_SV) + l * 64 + ch * 8;
            pack_store8(*(const float4*)pv, *(const float4*)(pv + 4),
                        smem + A_VH + adr128(0, l, ch));
        }
        __syncthreads();
        if (t + 1 < TILES) {  // prefetch next tile
            const size_t gbase = cta_base + (size_t)(t + 1) * 128 * 1024;
#pragma unroll
            for (int i = 0; i < 4; i++) {
                int c = tid + i * 512;
                size_t off = gbase + (size_t)(c >> 4) * 1024 + (c & 15) * 4;
                cp_async16(sb + A_SX + c * 16, k + off);
                cp_async16(sb + A_SV + c * 16, v + off);
            }
            CP_COMMIT();
        }
        // phi0 + store F0
        {
            float acc[8][4];
#pragma unroll
            for (int j = 0; j < 8; j++)
#pragma unroll
                for (int i = 0; i < 4; i++) acc[j][i] = 0.f;
            phi_pass(sb, A_XH, A_PH, acc, lg, quad, 0, lane);
            store_F(smem, A_F0, acc, lg, quad, lane);
        }
        __syncthreads();  // F0 visible
        // KV0, then phi1 + store F1 (overlapped region)
        kv_mma_pass(sb, A_F0, A_VH, kvacc[0], ksacc[0], onesb, mt, eh, lane);
        {
            float acc[8][4];
#pragma unroll
            for (int j = 0; j < 8; j++)
#pragma unroll
                for (int i = 0; i < 4; i++) acc[j][i] = 0.f;
            phi_pass(sb, A_XH, A_PH, acc, lg, quad, 1, lane);
            store_F(smem, A_F1, acc, lg, quad, lane);
        }
        __syncthreads();  // F1 visible
        kv_mma_pass(sb, A_F1, A_VH, kvacc[1], ksacc[1], onesb, mt, eh, lane);
    }
    // epilogue
    float* dst = g_KVpart + (size_t)(chunk * BH + bh) * M * E;
    const int r = lane >> 2, c2 = 2 * (lane & 3);
#pragma unroll
    for (int hf = 0; hf < 2; hf++)
#pragma unroll
        for (int n = 0; n < 4; n++) {
            int m0 = hf * 128 + mt * 16 + r;
            int e = eh * 32 + n * 8 + c2;
            *(float2*)(dst + m0 * 64 + e) = make_float2(kvacc[hf][n][0], kvacc[hf][n][1]);
            *(float2*)(dst + (m0 + 8) * 64 + e) = make_float2(kvacc[hf][n][2], kvacc[hf][n][3]);
        }
    if (eh == 0 && (lane & 3) == 0) {
        float* kd = g_Kspart + (size_t)(chunk * BH + bh) * M;
#pragma unroll
        for (int hf = 0; hf < 2; hf++) {
            kd[hf * 128 + mt * 16 + r] = ksacc[hf][0];
            kd[hf * 128 + mt * 16 + r + 8] = ksacc[hf][2];
        }
    }
}

// ============================ reduce: partials -> KVh fp16 + Ksum ============================
__global__ void reduce_kernel() {
    int idx = blockIdx.x * 256 + threadIdx.x;
    if (idx < BH * M * E) {
        float s = 0.f;
#pragma unroll
        for (int c = 0; c < NCHUNK; c++) s += g_KVpart[(size_t)c * BH * M * E + idx];
        g_KVh[idx] = __float2half_rn(s);
    }
    if (idx < BH * M) {
        float s = ZEPS;
#pragma unroll
        for (int c = 0; c < NCHUNK; c++) s += g_Kspart[(size_t)c * BH * M + idx];
        g_Ksum[idx] = s;
    }
}

// ============================ Kernel B: out = (Qf @ KV) * Z ============================
__global__ __launch_bounds__(512, 1) void out_kernel(const float* __restrict__ q,
                                                     const float* __restrict__ P,
                                                     float* __restrict__ out) {
    extern __shared__ char smem[];
    const uint32_t sb = smem_u32(smem);
    const int tid = threadIdx.x, w = tid >> 5, lane = tid & 31;
    const int ln = lane & 7, g2 = lane >> 3;
    const int bh = blockIdx.x, b = bh >> 4, hd = bh & 15;
    const int lg = w & 7, quad = w >> 3;  // phi roles
    const int lt = w & 7, eh = w >> 3;    // out roles
    const size_t cta_base = ((size_t)(b * L + blockIdx.y * (TILES * 128)) * H + hd) * 64;

    // prologue: KVh (full 256x64 fp16) + stage tile 0
#pragma unroll
    for (int i = 0; i < 4; i++) {
        int c = tid + i * 512;
        int m = c >> 3, ch = c & 7;
        cp_async16(sb + B_KVH + adr128(0, m, ch), g_KVh + (size_t)bh * 16384 + c * 8);
    }
#pragma unroll
    for (int i = 0; i < 4; i++) {
        int c = tid + i * 512;
        size_t off = cta_base + (size_t)(c >> 4) * 1024 + (c & 15) * 4;
        cp_async16(sb + B_SX + c * 16, q + off);
    }
    CP_COMMIT();
    load_P(P, smem, B_PH, tid);
    if (tid < 256) ((float*)(smem + B_KS))[tid] = g_Ksum[(size_t)bh * M + tid];
    const float* sKsm = (const float*)(smem + B_KS);

    for (int t = 0; t < TILES; t++) {
        CP_WAIT0();
        __syncthreads();
        for (int u = tid; u < 1024; u += 512) {
            int l = u >> 3, ch = u & 7;
            const float* px = (const float*)(smem + B_SX) + l * 64 + ch * 8;
            pack_store8(*(const float4*)px, *(const float4*)(px + 4),
                        smem + B_XH + adr128(0, l, ch));
        }
        __syncthreads();
        if (t + 1 < TILES) {
            const size_t gbase = cta_base + (size_t)(t + 1) * 128 * 1024;
#pragma unroll
            for (int i = 0; i < 4; i++) {
                int c = tid + i * 512;
                size_t off = gbase + (size_t)(c >> 4) * 1024 + (c & 15) * 4;
                cp_async16(sb + B_SX + c * 16, q + off);
            }
            CP_COMMIT();
        }
        float oacc[4][4];
#pragma unroll
        for (int n = 0; n < 4; n++)
#pragma unroll
            for (int i = 0; i < 4; i++) oacc[n][i] = 0.f;
        float zp0 = 0.f, zp1 = 0.f;

        // phi0 + store F0 + zp
        {
            float acc[8][4];
#pragma unroll
            for (int j = 0; j < 8; j++)
#pragma unroll
                for (int i = 0; i < 4; i++) acc[j][i] = 0.f;
            phi_pass(sb, B_XH, B_PH, acc, lg, quad, 0, lane);
            store_F(smem, B_F0, acc, lg, quad, lane);
#pragma unroll
            for (int j = 0; j < 8; j++) {
                int ml = quad * 64 + j * 8 + 2 * (lane & 3);
                zp0 += (fmaxf(acc[j][0], 0.f) + KEPS) * sKsm[ml] +
                       (fmaxf(acc[j][1], 0.f) + KEPS) * sKsm[ml + 1];
                zp1 += (fmaxf(acc[j][2], 0.f) + KEPS) * sKsm[ml] +
                       (fmaxf(acc[j][3], 0.f) + KEPS) * sKsm[ml + 1];
            }
        }
        __syncthreads();  // F0 visible
        // out0, then phi1 + F1 + zp (overlapped)
        {
            const int rowA = lt * 16 + ln + (g2 & 1) * 8;
#pragma unroll
            for (int kk = 0; kk < 8; kk++) {
                uint32_t qh[4];
                int cA = (2 * kk + (g2 >> 1)) ^ ln;
                ldsm_x4(sb + B_F0 + rowA * 256 + (cA << 4), qh);
                int rowB = kk * 16 + (g2 & 1) * 8 + ln;
#pragma unroll
                for (int n2 = 0; n2 < 2; n2++) {
                    uint32_t bkv[4];
                    int cB = (eh * 4 + n2 * 2 + (g2 >> 1)) ^ ln;
                    ldsm_x4t(sb + B_KVH + rowB * 128 + (cB << 4), bkv);
                    mma16816(oacc[n2 * 2], qh, bkv);
                    mma16816(oacc[n2 * 2 + 1], qh, bkv + 2);
                }
            }
        }
        {
            float acc[8][4];
#pragma unroll
            for (int j = 0; j < 8; j++)
#pragma unroll
                for (int i = 0; i < 4; i++) acc[j][i] = 0.f;
            phi_pass(sb, B_XH, B_PH, acc, lg, quad, 1, lane);
            store_F(smem, B_F1, acc, lg, quad, lane);
#pragma unroll
            for (int j = 0; j < 8; j++) {
                int ml = quad * 64 + j * 8 + 2 * (lane & 3);
                zp0 += (fmaxf(acc[j][0], 0.f) + KEPS) * sKsm[128 + ml] +
                       (fmaxf(acc[j][1], 0.f) + KEPS) * sKsm[128 + ml + 1];
                zp1 += (fmaxf(acc[j][2], 0.f) + KEPS) * sKsm[128 + ml] +
                       (fmaxf(acc[j][3], 0.f) + KEPS) * sKsm[128 + ml + 1];
            }
        }
        // zp reduce into sZp
        zp0 += __shfl_xor_sync(0xffffffffu, zp0, 1);
        zp0 += __shfl_xor_sync(0xffffffffu, zp0, 2);
        zp1 += __shfl_xor_sync(0xffffffffu, zp1, 1);
        zp1 += __shfl_xor_sync(0xffffffffu, zp1, 2);
        float* sZp = (float*)(smem + B_ZP);
        if ((lane & 3) == 0) {
            sZp[quad * 128 + lg * 16 + (lane >> 2)] = zp0;
            sZp[quad * 128 + lg * 16 + (lane >> 2) + 8] = zp1;
        }
        __syncthreads();  // F1 + sZp visible
        float* sZ = (float*)(smem + B_SZ);
        if (tid < 128) sZ[tid] = 1.0f / (sZp[tid] + sZp[128 + tid]);
        // out1
        {
            const int rowA = lt * 16 + ln + (g2 & 1) * 8;
#pragma unroll
            for (int kk = 0; kk < 8; kk++) {
                uint32_t qh[4];
                int cA = (2 * kk + (g2 >> 1)) ^ ln;
                ldsm_x4(sb + B_F1 + rowA * 256 + (cA << 4), qh);
                int rowB = 128 + kk * 16 + (g2 & 1) * 8 + ln;
#pragma unroll
                for (int n2 = 0; n2 < 2; n2++) {
                    uint32_t bkv[4];
                    int cB = (eh * 4 + n2 * 2 + (g2 >> 1)) ^ ln;
                    ldsm_x4t(sb + B_KVH + rowB * 128 + (cB << 4), bkv);
                    mma16816(oacc[n2 * 2], qh, bkv);
                    mma16816(oacc[n2 * 2 + 1], qh, bkv + 2);
                }
            }
        }
        __syncthreads();  // sZ visible to all
        // scale + store
        const int r = lane >> 2, c2 = 2 * (lane & 3);
        const int l0 = lt * 16 + r;
        float z0 = sZ[l0], z1 = sZ[l0 + 8];
        size_t ob = cta_base + (size_t)(t * 128 + l0) * 1024;
#pragma unroll
        for (int n = 0; n < 4; n++) {
            int e = eh * 32 + n * 8 + c2;
            *(float2*)(out + ob + e) = make_float2(oacc[n][0] * z0, oacc[n][1] * z0);
            *(float2*)(out + ob + 8 * 1024 + e) = make_float2(oacc[n][2] * z1, oacc[n][3] * z1);
        }
    }
}

extern "C" void kernel_launch(void* const* d_in, const int* in_sizes, int n_in,
                              void* d_out, int out_size) {
    const float* q = (const float*)d_in[0];
    const float* k = (const float*)d_in[1];
    const float* v = (const float*)d_in[2];
    const float* P = (const float*)d_in[3];
    float* out = (float*)d_out;

    cudaFuncSetAttribute(kv_kernel, cudaFuncAttributeMaxDynamicSharedMemorySize, SMEM_A);
    cudaFuncSetAttribute(out_kernel, cudaFuncAttributeMaxDynamicSharedMemorySize, SMEM_B);

    kv_kernel<<<dim3(BH, NCHUNK), 512, SMEM_A>>>(k, v, P);
    reduce_kernel<<<(BH * M * E + 255) / 256, 256>>>();
    out_kernel<<<dim3(BH, NCHUNK), 512, SMEM_B>>>(q, P, out);
}

// round 8
// speedup vs baseline: 6.9683x; 1.0084x over previous
#include <cuda_runtime.h>
#include <cuda_fp16.h>
#include <cstdint>

constexpr int B = 4, L = 4096, H = 16, D = 64, M = 256, E = 64;
constexpr int BH = 64;
constexpr int NCHUNK = 8;
constexpr int NTILES = 8;  // 64-row tiles per CTA
constexpr float SCALE = 0.35355339059327378f;  // 64^-0.25
constexpr float KEPS = 1e-3f;
constexpr float ZEPS = 1e-6f;

// ---- global scratch ----
__device__ float g_KVpart[(size_t)NCHUNK * BH * M * E];
__device__ float g_Kspart[(size_t)NCHUNK * BH * M];
__device__ __align__(16) __half g_KVh[(size_t)BH * M * E];
__device__ float g_Ksum[(size_t)BH * M];

// ---- smem byte offsets (kernel A) ----
constexpr int A_PH = 0, A_XH = 32768, A_VH0 = 40960, A_VH1 = 49152, A_F0 = 57344,
              A_F1 = 73728;
constexpr int SMEM_A = 90112;
// ---- smem byte offsets (kernel B) ----
constexpr int B_PH = 0, B_XH = 32768, B_F0 = 40960, B_F1 = 57344, B_KVH = 73728,
              B_KS = 106496, B_ZP = 107520, B_SZ = 108032;
constexpr int SMEM_B = 108288;

// ============================ low-level helpers ============================
__device__ __forceinline__ uint32_t smem_u32(const void* p) {
    uint32_t a;
    asm("{ .reg .u64 t; cvta.to.shared.u64 t, %1; cvt.u32.u64 %0, t; }" : "=r"(a) : "l"(p));
    return a;
}
__device__ __forceinline__ void ldsm_x4(uint32_t a, uint32_t r[4]) {
    asm volatile("ldmatrix.sync.aligned.m8n8.x4.shared.b16 {%0,%1,%2,%3}, [%4];"
                 : "=r"(r[0]), "=r"(r[1]), "=r"(r[2]), "=r"(r[3]) : "r"(a));
}
__device__ __forceinline__ void ldsm_x4t(uint32_t a, uint32_t r[4]) {
    asm volatile("ldmatrix.sync.aligned.m8n8.x4.trans.shared.b16 {%0,%1,%2,%3}, [%4];"
                 : "=r"(r[0]), "=r"(r[1]), "=r"(r[2]), "=r"(r[3]) : "r"(a));
}
__device__ __forceinline__ void mma16816(float c[4], const uint32_t a[4], const uint32_t b[2]) {
    asm volatile(
        "mma.sync.aligned.m16n8k16.row.col.f32.f16.f16.f32 "
        "{%0,%1,%2,%3}, {%4,%5,%6,%7}, {%8,%9}, {%0,%1,%2,%3};"
        : "+f"(c[0]), "+f"(c[1]), "+f"(c[2]), "+f"(c[3])
        : "r"(a[0]), "r"(a[1]), "r"(a[2]), "r"(a[3]), "r"(b[0]), "r"(b[1]));
}
__device__ __forceinline__ void cp_async16(uint32_t dst, const void* src) {
    asm volatile("cp.async.cg.shared.global [%0], [%1], 16;" ::"r"(dst), "l"(src));
}
#define CP_COMMIT() asm volatile("cp.async.commit_group;" ::: "memory")
#define CP_WAIT0() asm volatile("cp.async.wait_group 0;" ::: "memory")

__device__ __forceinline__ uint32_t packh2(float x, float y) {
    __half2 h = __floats2half2_rn(x, y);
    return *(uint32_t*)&h;
}
__device__ __forceinline__ void pack_store8(float4 a, float4 b, char* hp) {
    uint4 hv;
    hv.x = packh2(a.x, a.y);
    hv.y = packh2(a.z, a.w);
    hv.z = packh2(b.x, b.y);
    hv.w = packh2(b.z, b.w);
    *(uint4*)hp = hv;
}
__device__ __forceinline__ uint32_t adr128(uint32_t base, int row, int chunk) {
    return base + row * 128 + ((chunk ^ (row & 7)) << 4);
}
__device__ __forceinline__ uint32_t adr256(uint32_t base, int row, int chunk) {
    return base + row * 256 + ((chunk ^ (row & 7)) << 4);
}

// load P (scaled), fp16, SW layout [256 rows x 128B]
__device__ __forceinline__ void load_P(const float* __restrict__ P, char* smem, int PHo,
                                       int tid, int nthr) {
    for (int u = tid; u < 2048; u += nthr) {
        int m = u >> 3, ch = u & 7;
        float4 p0 = *(const float4*)(P + m * 64 + ch * 8);
        float4 p1 = *(const float4*)(P + m * 64 + ch * 8 + 4);
        p0.x *= SCALE; p0.y *= SCALE; p0.z *= SCALE; p0.w *= SCALE;
        p1.x *= SCALE; p1.y *= SCALE; p1.z *= SCALE; p1.w *= SCALE;
        pack_store8(p0, p1, smem + PHo + adr128(0, m, ch));
    }
}

// phi: acc += X(64lx64d) @ P^T block; warp block = 16l (lg) x 64m (quad, within hf)
__device__ __forceinline__ void phi_pass(uint32_t sb, int XHo, int PHo, float acc[8][4],
                                         int lg, int quad, int hf, int lane) {
    const int ln = lane & 7, g2 = lane >> 3;
    const int rowA = lg * 16 + ln + (g2 & 1) * 8;
    const int rowB = hf * 128 + quad * 64 + (g2 >> 1) * 8 + ln;
#pragma unroll
    for (int kk = 0; kk < 4; kk++) {
        uint32_t ah[4];
        int cA = (2 * kk + (g2 >> 1)) ^ ln;
        ldsm_x4(sb + XHo + rowA * 128 + (cA << 4), ah);
        int cB = (2 * kk + (g2 & 1)) ^ ln;
        uint32_t pb = sb + PHo + rowB * 128 + (cB << 4);
#pragma unroll
        for (int j2 = 0; j2 < 4; j2++) {
            uint32_t b4[4];
            ldsm_x4(pb + j2 * 2048, b4);
            mma16816(acc[2 * j2], ah, b4);
            mma16816(acc[2 * j2 + 1], ah, b4 + 2);
        }
    }
}

// relu+eps and pack F fragment to smem buffer Fo (64 rows x 256B)
__device__ __forceinline__ void store_F(char* smem, int Fo, const float acc[8][4], int lg,
                                        int quad, int lane) {
    const int r0 = lg * 16 + (lane >> 2);
#pragma unroll
    for (int j = 0; j < 8; j++) {
        int ml = quad * 64 + j * 8 + 2 * (lane & 3);
        float f0 = fmaxf(acc[j][0], 0.f) + KEPS;
        float f1 = fmaxf(acc[j][1], 0.f) + KEPS;
        float f2 = fmaxf(acc[j][2], 0.f) + KEPS;
        float f3 = fmaxf(acc[j][3], 0.f) + KEPS;
        *(uint32_t*)(smem + Fo + adr256(0, r0, ml >> 3) + (ml & 7) * 2) = packh2(f0, f1);
        *(uint32_t*)(smem + Fo + adr256(0, r0 + 8, ml >> 3) + (ml & 7) * 2) = packh2(f2, f3);
    }
}

// KV pass: kvacc[mf][nf] += F^T @ V (K=64), ksacc[mf] += F^T @ ones
// warp tile 32m (mt) x 32e (eh)
__device__ __forceinline__ void kv_mma_pass(uint32_t sb, int Fo, int Vo, float kvacc[2][4][4],
                                            float ksacc[2][4], const uint32_t onesb[2],
                                            int mt, int eh, int lane) {
    const int ln = lane & 7, g2 = lane >> 3;
#pragma unroll
    for (int kk = 0; kk < 4; kk++) {
        uint32_t fh[2][4];
        int rowAt = kk * 16 + (g2 >> 1) * 8 + ln;
#pragma unroll
        for (int mf = 0; mf < 2; mf++) {
            int cAt = (2 * (2 * mt + mf) + (g2 & 1)) ^ ln;
            ldsm_x4t(sb + Fo + rowAt * 256 + (cAt << 4), fh[mf]);
        }
        int rowBt = kk * 16 + (g2 & 1) * 8 + ln;
        uint32_t bv[2][4];
#pragma unroll
        for (int n2 = 0; n2 < 2; n2++) {
            int cBt = (eh * 4 + n2 * 2 + (g2 >> 1)) ^ ln;
            ldsm_x4t(sb + Vo + rowBt * 128 + (cBt << 4), bv[n2]);
        }
#pragma unroll
        for (int mf = 0; mf < 2; mf++) {
#pragma unroll
            for (int n2 = 0; n2 < 2; n2++) {
                mma16816(kvacc[mf][n2 * 2], fh[mf], bv[n2]);
                mma16816(kvacc[mf][n2 * 2 + 1], fh[mf], bv[n2] + 2);
            }
            mma16816(ksacc[mf], fh[mf], onesb);
        }
    }
}

// ============================ Kernel A: KV + Ksum partials ============================
__global__ __launch_bounds__(256, 2) void kv_kernel(const float* __restrict__ k,
                                                    const float* __restrict__ v,
                                                    const float* __restrict__ P) {
    extern __shared__ char smem[];
    const uint32_t sb = smem_u32(smem);
    const int tid = threadIdx.x, w = tid >> 5, lane = tid & 31;
    const int bh = blockIdx.x, b = bh >> 4, hd = bh & 15;
    const int chunk = blockIdx.y;
    const int lg = w & 3, quad = w >> 2;  // phi roles (4 x 2)
    const int mt = w & 3, eh = w >> 2;    // KV roles (4 x 2)
    const size_t cta_base = ((size_t)(b * L + chunk * (NTILES * 64)) * H + hd) * 64;

    load_P(P, smem, A_PH, tid, 256);

    float kvacc[2][2][4][4];
    float ksacc[2][2][4];
#pragma unroll
    for (int a = 0; a < 2; a++)
#pragma unroll
        for (int mf = 0; mf < 2; mf++) {
#pragma unroll
            for (int i = 0; i < 4; i++) ksacc[a][mf][i] = 0.f;
#pragma unroll
            for (int n = 0; n < 4; n++)
#pragma unroll
                for (int i = 0; i < 4; i++) kvacc[a][mf][n][i] = 0.f;
        }
    const uint32_t onesb[2] = {0x3C003C00u, 0x3C003C00u};

    for (int t = 0; t < NTILES; t++) {
        const int vbuf = (t & 1) ? A_VH1 : A_VH0;
        const size_t tbase = cta_base + (size_t)t * 64 * 1024;
        // LDG -> convert -> STS (X single buffer, V double buffer)
#pragma unroll
        for (int u = tid; u < 512; u += 256) {
            int l = u >> 3, ch = u & 7;
            size_t gi = tbase + (size_t)l * 1024 + ch * 8;
            float4 x0 = *(const float4*)(k + gi);
            float4 x1 = *(const float4*)(k + gi + 4);
            float4 v0 = *(const float4*)(v + gi);
            float4 v1 = *(const float4*)(v + gi + 4);
            pack_store8(x0, x1, smem + A_XH + adr128(0, l, ch));
            pack_store8(v0, v1, smem + vbuf + adr128(0, l, ch));
        }
        __syncthreads();  // X/V visible
        // phi0 + store F0
        {
            float acc[8][4];
#pragma unroll
            for (int j = 0; j < 8; j++)
#pragma unroll
                for (int i = 0; i < 4; i++) acc[j][i] = 0.f;
            phi_pass(sb, A_XH, A_PH, acc, lg, quad, 0, lane);
            store_F(smem, A_F0, acc, lg, quad, lane);
        }
        __syncthreads();  // F0 visible
        // KV0, then phi1 + F1
        kv_mma_pass(sb, A_F0, vbuf, kvacc[0], ksacc[0], onesb, mt, eh, lane);
        {
            float acc[8][4];
#pragma unroll
            for (int j = 0; j < 8; j++)
#pragma unroll
                for (int i = 0; i < 4; i++) acc[j][i] = 0.f;
            phi_pass(sb, A_XH, A_PH, acc, lg, quad, 1, lane);
            store_F(smem, A_F1, acc, lg, quad, lane);
        }
        __syncthreads();  // F1 visible
        kv_mma_pass(sb, A_F1, vbuf, kvacc[1], ksacc[1], onesb, mt, eh, lane);
    }
    // epilogue
    float* dst = g_KVpart + (size_t)(chunk * BH + bh) * M * E;
    const int r = lane >> 2, c2 = 2 * (lane & 3);
#pragma unroll
    for (int hf = 0; hf < 2; hf++)
#pragma unroll
        for (int mf = 0; mf < 2; mf++)
#pragma unroll
            for (int n = 0; n < 4; n++) {
                int m0 = hf * 128 + mt * 32 + mf * 16 + r;
                int e = eh * 32 + n * 8 + c2;
                *(float2*)(dst + m0 * 64 + e) =
                    make_float2(kvacc[hf][mf][n][0], kvacc[hf][mf][n][1]);
                *(float2*)(dst + (m0 + 8) * 64 + e) =
                    make_float2(kvacc[hf][mf][n][2], kvacc[hf][mf][n][3]);
            }
    if (eh == 0 && (lane & 3) == 0) {
        float* kd = g_Kspart + (size_t)(chunk * BH + bh) * M;
#pragma unroll
        for (int hf = 0; hf < 2; hf++)
#pragma unroll
            for (int mf = 0; mf < 2; mf++) {
                kd[hf * 128 + mt * 32 + mf * 16 + r] = ksacc[hf][mf][0];
                kd[hf * 128 + mt * 32 + mf * 16 + r + 8] = ksacc[hf][mf][2];
            }
    }
}

// ============================ reduce: partials -> KVh fp16 + Ksum ============================
__global__ void reduce_kernel() {
    int idx = blockIdx.x * 256 + threadIdx.x;
    if (idx < BH * M * E) {
        float s = 0.f;
#pragma unroll
        for (int c = 0; c < NCHUNK; c++) s += g_KVpart[(size_t)c * BH * M * E + idx];
        g_KVh[idx] = __float2half_rn(s);
    }
    if (idx < BH * M) {
        float s = ZEPS;
#pragma unroll
        for (int c = 0; c < NCHUNK; c++) s += g_Kspart[(size_t)c * BH * M + idx];
        g_Ksum[idx] = s;
    }
}

// ============================ Kernel B: out = (Qf @ KV) * Z ============================
__global__ __launch_bounds__(256, 2) void out_kernel(const float* __restrict__ q,
                                                     const float* __restrict__ P,
                                                     float* __restrict__ out) {
    extern __shared__ char smem[];
    const uint32_t sb = smem_u32(smem);
    const int tid = threadIdx.x, w = tid >> 5, lane = tid & 31;
    const int ln = lane & 7, g2 = lane >> 3;
    const int bh = blockIdx.x, b = bh >> 4, hd = bh & 15;
    const int lg = w & 3, quad = w >> 2;  // phi roles
    const int lt = w & 3, eh = w >> 2;    // out roles (16l x 32e)
    const size_t cta_base = ((size_t)(b * L + blockIdx.y * (NTILES * 64)) * H + hd) * 64;

    // prologue: KVh (256x64 fp16) via cp.async
#pragma unroll
    for (int i = 0; i < 8; i++) {
        int c = tid + i * 256;
        int m = c >> 3, ch = c & 7;
        cp_async16(sb + B_KVH + adr128(0, m, ch), g_KVh + (size_t)bh * 16384 + c * 8);
    }
    CP_COMMIT();
    load_P(P, smem, B_PH, tid, 256);
    ((float*)(smem + B_KS))[tid] = g_Ksum[(size_t)bh * M + tid];
    const float* sKsm = (const float*)(smem + B_KS);
    CP_WAIT0();

    for (int t = 0; t < NTILES; t++) {
        const size_t tbase = cta_base + (size_t)t * 64 * 1024;
#pragma unroll
        for (int u = tid; u < 512; u += 256) {
            int l = u >> 3, ch = u & 7;
            size_t gi = tbase + (size_t)l * 1024 + ch * 8;
            float4 x0 = *(const float4*)(q + gi);
            float4 x1 = *(const float4*)(q + gi + 4);
            pack_store8(x0, x1, smem + B_XH + adr128(0, l, ch));
        }
        __syncthreads();  // X visible (also KVh on t=0)
        float oacc[4][4];
#pragma unroll
        for (int n = 0; n < 4; n++)
#pragma unroll
            for (int i = 0; i < 4; i++) oacc[n][i] = 0.f;
        float zp0 = 0.f, zp1 = 0.f;
        // phi0 + F0 + zp
        {
            float acc[8][4];
#pragma unroll
            for (int j = 0; j < 8; j++)
#pragma unroll
                for (int i = 0; i < 4; i++) acc[j][i] = 0.f;
            phi_pass(sb, B_XH, B_PH, acc, lg, quad, 0, lane);
            store_F(smem, B_F0, acc, lg, quad, lane);
#pragma unroll
            for (int j = 0; j < 8; j++) {
                int ml = quad * 64 + j * 8 + 2 * (lane & 3);
                zp0 += (fmaxf(acc[j][0], 0.f) + KEPS) * sKsm[ml] +
                       (fmaxf(acc[j][1], 0.f) + KEPS) * sKsm[ml + 1];
                zp1 += (fmaxf(acc[j][2], 0.f) + KEPS) * sKsm[ml] +
                       (fmaxf(acc[j][3], 0.f) + KEPS) * sKsm[ml + 1];
            }
        }
        __syncthreads();  // F0 visible
        // out0 (K = m 0..127), then phi1 + F1 + zp
        {
            const int rowA = lt * 16 + ln + (g2 & 1) * 8;
#pragma unroll
            for (int kk = 0; kk < 8; kk++) {
                uint32_t qh[4];
                int cA = (2 * kk + (g2 >> 1)) ^ ln;
                ldsm_x4(sb + B_F0 + rowA * 256 + (cA << 4), qh);
                int rowB = kk * 16 + (g2 & 1) * 8 + ln;
#pragma unroll
                for (int n2 = 0; n2 < 2; n2++) {
                    uint32_t bkv[4];
                    int cB = (eh * 4 + n2 * 2 + (g2 >> 1)) ^ ln;
                    ldsm_x4t(sb + B_KVH + rowB * 128 + (cB << 4), bkv);
                    mma16816(oacc[n2 * 2], qh, bkv);
                    mma16816(oacc[n2 * 2 + 1], qh, bkv + 2);
                }
            }
        }
        {
            float acc[8][4];
#pragma unroll
            for (int j = 0; j < 8; j++)
#pragma unroll
                for (int i = 0; i < 4; i++) acc[j][i] = 0.f;
            phi_pass(sb, B_XH, B_PH, acc, lg, quad, 1, lane);
            store_F(smem, B_F1, acc, lg, quad, lane);
#pragma unroll
            for (int j = 0; j < 8; j++) {
                int ml = quad * 64 + j * 8 + 2 * (lane & 3);
                zp0 += (fmaxf(acc[j][0], 0.f) + KEPS) * sKsm[128 + ml] +
                       (fmaxf(acc[j][1], 0.f) + KEPS) * sKsm[128 + ml + 1];
                zp1 += (fmaxf(acc[j][2], 0.f) + KEPS) * sKsm[128 + ml] +
                       (fmaxf(acc[j][3], 0.f) + KEPS) * sKsm[128 + ml + 1];
            }
        }
        // zp reduce (4 threads share a row)
        zp0 += __shfl_xor_sync(0xffffffffu, zp0, 1);
        zp0 += __shfl_xor_sync(0xffffffffu, zp0, 2);
        zp1 += __shfl_xor_sync(0xffffffffu, zp1, 1);
        zp1 += __shfl_xor_sync(0xffffffffu, zp1, 2);
        float* sZp = (float*)(smem + B_ZP);
        if ((lane & 3) == 0) {
            sZp[quad * 64 + lg * 16 + (lane >> 2)] = zp0;
            sZp[quad * 64 + lg * 16 + (lane >> 2) + 8] = zp1;
        }
        __syncthreads();  // F1 + sZp visible
        float* sZ = (float*)(smem + B_SZ);
        if (tid < 64) sZ[tid] = 1.0f / (sZp[tid] + sZp[64 + tid]);
        // out1 (K = m 128..255)
        {
            const int rowA = lt * 16 + ln + (g2 & 1) * 8;
#pragma unroll
            for (int kk = 0; kk < 8; kk++) {
                uint32_t qh[4];
                int cA = (2 * kk + (g2 >> 1)) ^ ln;
                ldsm_x4(sb + B_F1 + rowA * 256 + (cA << 4), qh);
                int rowB = 128 + kk * 16 + (g2 & 1) * 8 + ln;
#pragma unroll
                for (int n2 = 0; n2 < 2; n2++) {
                    uint32_t bkv[4];
                    int cB = (eh * 4 + n2 * 2 + (g2 >> 1)) ^ ln;
                    ldsm_x4t(sb + B_KVH + rowB * 128 + (cB << 4), bkv);
                    mma16816(oacc[n2 * 2], qh, bkv);
                    mma16816(oacc[n2 * 2 + 1], qh, bkv + 2);
                }
            }
        }
        __syncthreads();  // sZ visible
        // scale + store
        const int r = lane >> 2, c2 = 2 * (lane & 3);
        const int l0 = lt * 16 + r;
        float z0 = sZ[l0], z1 = sZ[l0 + 8];
        size_t ob = tbase + (size_t)l0 * 1024;
#pragma unroll
        for (int n = 0; n < 4; n++) {
            int e = eh * 32 + n * 8 + c2;
            *(float2*)(out + ob + e) = make_float2(oacc[n][0] * z0, oacc[n][1] * z0);
            *(float2*)(out + ob + 8 * 1024 + e) = make_float2(oacc[n][2] * z1, oacc[n][3] * z1);
        }
    }
}

extern "C" void kernel_launch(void* const* d_in, const int* in_sizes, int n_in,
                              void* d_out, int out_size) {
    const float* q = (const float*)d_in[0];
    const float* k = (const float*)d_in[1];
    const float* v = (const float*)d_in[2];
    const float* P = (const float*)d_in[3];
    float* out = (float*)d_out;

    cudaFuncSetAttribute(kv_kernel, cudaFuncAttributeMaxDynamicSharedMemorySize, SMEM_A);
    cudaFuncSetAttribute(out_kernel, cudaFuncAttributeMaxDynamicSharedMemorySize, SMEM_B);

    kv_kernel<<<dim3(BH, NCHUNK), 256, SMEM_A>>>(k, v, P);
    reduce_kernel<<<(BH * M * E + 255) / 256, 256>>>();
    out_kernel<<<dim3(BH, NCHUNK), 256, SMEM_B>>>(q, P, out);
}

// round 11
// speedup vs baseline: 7.2492x; 1.0403x over previous
#include <cuda_runtime.h>
#include <cuda_fp16.h>
#include <cstdint>

constexpr int B = 4, L = 4096, H = 16, D = 64, M = 256, E = 64;
constexpr int BH = 64;
constexpr int NCHUNK = 8;
constexpr float SCALE = 0.35355339059327378f;  // 64^-0.25
constexpr float KEPS = 1e-3f;
constexpr float ZEPS = 1e-6f;

// ---- global scratch ----
__device__ float g_KVpart[(size_t)NCHUNK * BH * M * E];
__device__ float g_Kspart[(size_t)NCHUNK * BH * M];
__device__ __align__(16) __half g_KVh[(size_t)BH * M * E];
__device__ float g_Ksum[(size_t)BH * M];

// ---- smem byte offsets (kernel A: M-split, 128-row tiles) ----
constexpr int A_P = 0, A_X = 16384, A_V = 32768, A_F = 49152;
constexpr int SMEM_A = 81920;
// ---- smem byte offsets (kernel B: 64-row tiles) ----
constexpr int B_P = 0, B_X = 32768, B_F = 40960, B_KV = 73728, B_KS = 106496,
              B_ZP = 107520, B_SZ = 108544;
constexpr int SMEM_B = 108800;

// ============================ low-level helpers ============================
__device__ __forceinline__ uint32_t smem_u32(const void* p) {
    uint32_t a;
    asm("{ .reg .u64 t; cvta.to.shared.u64 t, %1; cvt.u32.u64 %0, t; }" : "=r"(a) : "l"(p));
    return a;
}
__device__ __forceinline__ void ldsm_x4(uint32_t a, uint32_t r[4]) {
    asm volatile("ldmatrix.sync.aligned.m8n8.x4.shared.b16 {%0,%1,%2,%3}, [%4];"
                 : "=r"(r[0]), "=r"(r[1]), "=r"(r[2]), "=r"(r[3]) : "r"(a));
}
__device__ __forceinline__ void ldsm_x4t(uint32_t a, uint32_t r[4]) {
    asm volatile("ldmatrix.sync.aligned.m8n8.x4.trans.shared.b16 {%0,%1,%2,%3}, [%4];"
                 : "=r"(r[0]), "=r"(r[1]), "=r"(r[2]), "=r"(r[3]) : "r"(a));
}
__device__ __forceinline__ void mma16816(float c[4], const uint32_t a[4], const uint32_t b[2]) {
    asm volatile(
        "mma.sync.aligned.m16n8k16.row.col.f32.f16.f16.f32 "
        "{%0,%1,%2,%3}, {%4,%5,%6,%7}, {%8,%9}, {%0,%1,%2,%3};"
        : "+f"(c[0]), "+f"(c[1]), "+f"(c[2]), "+f"(c[3])
        : "r"(a[0]), "r"(a[1]), "r"(a[2]), "r"(a[3]), "r"(b[0]), "r"(b[1]));
}
__device__ __forceinline__ void cp_async16(uint32_t dst, const void* src) {
    asm volatile("cp.async.cg.shared.global [%0], [%1], 16;" ::"r"(dst), "l"(src));
}
#define CP_COMMIT() asm volatile("cp.async.commit_group;" ::: "memory")
#define CP_WAIT0() asm volatile("cp.async.wait_group 0;" ::: "memory")

__device__ __forceinline__ uint32_t packh2(float x, float y) {
    __half2 h = __floats2half2_rn(x, y);
    return *(uint32_t*)&h;
}
__device__ __forceinline__ void pack_store8(float4 a, float4 b, char* hp) {
    uint4 hv;
    hv.x = packh2(a.x, a.y);
    hv.y = packh2(a.z, a.w);
    hv.z = packh2(b.x, b.y);
    hv.w = packh2(b.z, b.w);
    *(uint4*)hp = hv;
}
__device__ __forceinline__ uint32_t adr128(uint32_t base, int row, int chunk) {
    return base + row * 128 + ((chunk ^ (row & 7)) << 4);
}
__device__ __forceinline__ uint32_t adr256(uint32_t base, int row, int chunk) {
    return base + row * 256 + ((chunk ^ (row & 7)) << 4);
}
__device__ __forceinline__ uint32_t adr512(uint32_t base, int row, int chunk) {
    return base + row * 512 + ((chunk ^ (row & 7)) << 4);
}

// ============================ Kernel A: KV + Ksum partials (M-split) ============================
__global__ __launch_bounds__(256, 2) void kv_kernel(const float* __restrict__ k,
                                                    const float* __restrict__ v,
                                                    const float* __restrict__ P) {
    extern __shared__ char smem[];
    const uint32_t sb = smem_u32(smem);
    const int tid = threadIdx.x, w = tid >> 5, lane = tid & 31;
    const int ln = lane & 7, g2 = lane >> 3;
    const int bh = blockIdx.x, b = bh >> 4, hd = bh & 15;
    const int chunk = blockIdx.y, mhalf = blockIdx.z;
    const int lg = w & 3, quad = w >> 2;  // phi: rows lg*32, m-block quad*64 (in half)
    const int mt = w & 3, eh = w >> 2;    // KV: m mt*32, e eh*32
    const size_t cta_base = ((size_t)(b * L + chunk * 512) * H + hd) * 64;

    // load P half (scaled), fp16, [128 rows x 128B]
    for (int u = tid; u < 1024; u += 256) {
        int ml = u >> 3, ch = u & 7;
        int mg = mhalf * 128 + ml;
        float4 p0 = *(const float4*)(P + mg * 64 + ch * 8);
        float4 p1 = *(const float4*)(P + mg * 64 + ch * 8 + 4);
        p0.x *= SCALE; p0.y *= SCALE; p0.z *= SCALE; p0.w *= SCALE;
        p1.x *= SCALE; p1.y *= SCALE; p1.z *= SCALE; p1.w *= SCALE;
        pack_store8(p0, p1, smem + A_P + adr128(0, ml, ch));
    }

    float kvacc[2][4][4];
    float ksacc[2][4];
#pragma unroll
    for (int mf = 0; mf < 2; mf++) {
#pragma unroll
        for (int i = 0; i < 4; i++) ksacc[mf][i] = 0.f;
#pragma unroll
        for (int n = 0; n < 4; n++)
#pragma unroll
            for (int i = 0; i < 4; i++) kvacc[mf][n][i] = 0.f;
    }
    const uint32_t onesb[2] = {0x3C003C00u, 0x3C003C00u};

    for (int t = 0; t < 4; t++) {
        const size_t tbase = cta_base + (size_t)t * 128 * 1024;
        // LDG -> convert -> STS (128 rows of k and v)
#pragma unroll
        for (int i = 0; i < 4; i++) {
            int c = tid + i * 256;
            int l = c >> 3, ch = c & 7;
            size_t gi = tbase + (size_t)l * 1024 + ch * 8;
            float4 x0 = *(const float4*)(k + gi);
            float4 x1 = *(const float4*)(k + gi + 4);
            float4 v0 = *(const float4*)(v + gi);
            float4 v1 = *(const float4*)(v + gi + 4);
            pack_store8(x0, x1, smem + A_X + adr128(0, l, ch));
            pack_store8(v0, v1, smem + A_V + adr128(0, l, ch));
        }
        __syncthreads();  // X/V visible (also: prior KV done reading V/F)
        // phi: warp computes 32l x 64m, K=64
        {
            float acc[16][4];
#pragma unroll
            for (int j = 0; j < 16; j++)
#pragma unroll
                for (int i = 0; i < 4; i++) acc[j][i] = 0.f;
            const int R0 = lg * 32, MB = quad * 64;
            const int rowA0 = R0 + ln + (g2 & 1) * 8;
#pragma unroll
            for (int kk = 0; kk < 4; kk++) {
                uint32_t a0[4], a1[4];
                int cA = (2 * kk + (g2 >> 1)) ^ ln;
                ldsm_x4(sb + A_X + rowA0 * 128 + (cA << 4), a0);
                ldsm_x4(sb + A_X + (rowA0 + 16) * 128 + (cA << 4), a1);
                int cB = (2 * kk + (g2 & 1)) ^ ln;
#pragma unroll
                for (int j2 = 0; j2 < 4; j2++) {
                    uint32_t b4[4];
                    int rowB = MB + j2 * 16 + (g2 >> 1) * 8 + ln;
                    ldsm_x4(sb + A_P + rowB * 128 + (cB << 4), b4);
                    mma16816(acc[2 * j2], a0, b4);
                    mma16816(acc[2 * j2 + 1], a0, b4 + 2);
                    mma16816(acc[8 + 2 * j2], a1, b4);
                    mma16816(acc[8 + 2 * j2 + 1], a1, b4 + 2);
                }
            }
            // relu+eps, pack to F [128 rows x 256B]
#pragma unroll
            for (int lsub = 0; lsub < 2; lsub++) {
                int r0 = R0 + lsub * 16 + (lane >> 2);
#pragma unroll
                for (int j = 0; j < 8; j++) {
                    int ml = MB + j * 8 + 2 * (lane & 3);
                    const float* a = acc[lsub * 8 + j];
                    float f0 = fmaxf(a[0], 0.f) + KEPS;
                    float f1 = fmaxf(a[1], 0.f) + KEPS;
                    float f2 = fmaxf(a[2], 0.f) + KEPS;
                    float f3 = fmaxf(a[3], 0.f) + KEPS;
                    *(uint32_t*)(smem + A_F + adr256(0, r0, ml >> 3) + (ml & 7) * 2) =
                        packh2(f0, f1);
                    *(uint32_t*)(smem + A_F + adr256(0, r0 + 8, ml >> 3) + (ml & 7) * 2) =
                        packh2(f2, f3);
                }
            }
        }
        __syncthreads();  // F visible
        // KV: kvacc += F^T @ V over 128 l-rows; ksacc += F^T @ ones
#pragma unroll
        for (int kk = 0; kk < 8; kk++) {
            uint32_t fh[2][4];
            int rowAt = kk * 16 + (g2 >> 1) * 8 + ln;
#pragma unroll
            for (int mf = 0; mf < 2; mf++) {
                int cAt = (2 * (2 * mt + mf) + (g2 & 1)) ^ ln;
                ldsm_x4t(sb + A_F + rowAt * 256 + (cAt << 4), fh[mf]);
            }
            int rowBt = kk * 16 + (g2 & 1) * 8 + ln;
            uint32_t bv[2][4];
#pragma unroll
            for (int n2 = 0; n2 < 2; n2++) {
                int cBt = (eh * 4 + n2 * 2 + (g2 >> 1)) ^ ln;
                ldsm_x4t(sb + A_V + rowBt * 128 + (cBt << 4), bv[n2]);
            }
#pragma unroll
            for (int mf = 0; mf < 2; mf++) {
                mma16816(kvacc[mf][0], fh[mf], bv[0]);
                mma16816(kvacc[mf][1], fh[mf], bv[0] + 2);
                mma16816(kvacc[mf][2], fh[mf], bv[1]);
                mma16816(kvacc[mf][3], fh[mf], bv[1] + 2);
                mma16816(ksacc[mf], fh[mf], onesb);
            }
        }
        __syncthreads();  // F/V consumed, safe to overwrite next tile
    }
    // epilogue: write this half's partials
    float* dst = g_KVpart + (size_t)(chunk * BH + bh) * M * E + mhalf * 128 * 64;
    const int r = lane >> 2, c2 = 2 * (lane & 3);
#pragma unroll
    for (int mf = 0; mf < 2; mf++)
#pragma unroll
        for (int n = 0; n < 4; n++) {
            int m0 = mt * 32 + mf * 16 + r;
            int e = eh * 32 + n * 8 + c2;
            *(float2*)(dst + m0 * 64 + e) = make_float2(kvacc[mf][n][0], kvacc[mf][n][1]);
            *(float2*)(dst + (m0 + 8) * 64 + e) = make_float2(kvacc[mf][n][2], kvacc[mf][n][3]);
        }
    if (eh == 0 && (lane & 3) == 0) {
        float* kd = g_Kspart + (size_t)(chunk * BH + bh) * M + mhalf * 128;
#pragma unroll
        for (int mf = 0; mf < 2; mf++) {
            kd[mt * 32 + mf * 16 + r] = ksacc[mf][0];
            kd[mt * 32 + mf * 16 + r + 8] = ksacc[mf][2];
        }
    }
}

// ============================ reduce: partials -> KVh fp16 + Ksum ============================
__global__ void reduce_kernel() {
    int idx = blockIdx.x * 256 + threadIdx.x;
    if (idx < BH * M * E) {
        float s = 0.f;
#pragma unroll
        for (int c = 0; c < NCHUNK; c++) s += g_KVpart[(size_t)c * BH * M * E + idx];
        g_KVh[idx] = __float2half_rn(s);
    }
    if (idx < BH * M) {
        float s = ZEPS;
#pragma unroll
        for (int c = 0; c < NCHUNK; c++) s += g_Kspart[(size_t)c * BH * M + idx];
        g_Ksum[idx] = s;
    }
}

// ============================ Kernel B: out = (Qf @ KV) * Z ============================
__global__ __launch_bounds__(256, 2) void out_kernel(const float* __restrict__ q,
                                                     const float* __restrict__ P,
                                                     float* __restrict__ out) {
    extern __shared__ char smem[];
    const uint32_t sb = smem_u32(smem);
    const int tid = threadIdx.x, w = tid >> 5, lane = tid & 31;
    const int ln = lane & 7, g2 = lane >> 3;
    const int bh = blockIdx.x, b = bh >> 4, hd = bh & 15;
    const int lg = w & 1, mb = w >> 1;  // phi: rows lg*32, m-block mb*64
    const int lt = w & 3, eh = w >> 2;  // out: rows lt*16, e eh*32
    const size_t cta_base = ((size_t)(b * L + blockIdx.y * 512) * H + hd) * 64;

    // prologue: KVh (256x64 fp16) via cp.async
#pragma unroll
    for (int i = 0; i < 8; i++) {
        int c = tid + i * 256;
        int m = c >> 3, ch = c & 7;
        cp_async16(sb + B_KV + adr128(0, m, ch), g_KVh + (size_t)bh * 16384 + c * 8);
    }
    CP_COMMIT();
    // P full (scaled) fp16 [256 rows x 128B]
    for (int u = tid; u < 2048; u += 256) {
        int m = u >> 3, ch = u & 7;
        float4 p0 = *(const float4*)(P + m * 64 + ch * 8);
        float4 p1 = *(const float4*)(P + m * 64 + ch * 8 + 4);
        p0.x *= SCALE; p0.y *= SCALE; p0.z *= SCALE; p0.w *= SCALE;
        p1.x *= SCALE; p1.y *= SCALE; p1.z *= SCALE; p1.w *= SCALE;
        pack_store8(p0, p1, smem + B_P + adr128(0, m, ch));
    }
    ((float*)(smem + B_KS))[tid] = g_Ksum[(size_t)bh * M + tid];
    const float* sKsm = (const float*)(smem + B_KS);
    CP_WAIT0();

    for (int t = 0; t < 8; t++) {
        const size_t tbase = cta_base + (size_t)t * 64 * 1024;
        // LDG q -> convert -> STS (64 rows)
#pragma unroll
        for (int i = 0; i < 2; i++) {
            int c = tid + i * 256;
            int l = c >> 3, ch = c & 7;
            size_t gi = tbase + (size_t)l * 1024 + ch * 8;
            float4 x0 = *(const float4*)(q + gi);
            float4 x1 = *(const float4*)(q + gi + 4);
            pack_store8(x0, x1, smem + B_X + adr128(0, l, ch));
        }
        __syncthreads();  // X visible (KV prologue also, on t=0)
        // phi: warp 32l x 64m, K=64 ; F [64 rows x 512B], zp partials
        float zp[2][2] = {{0.f, 0.f}, {0.f, 0.f}};
        {
            float acc[16][4];
#pragma unroll
            for (int j = 0; j < 16; j++)
#pragma unroll
                for (int i = 0; i < 4; i++) acc[j][i] = 0.f;
            const int R0 = lg * 32, MB = mb * 64;
            const int rowA0 = R0 + ln + (g2 & 1) * 8;
#pragma unroll
            for (int kk = 0; kk < 4; kk++) {
                uint32_t a0[4], a1[4];
                int cA = (2 * kk + (g2 >> 1)) ^ ln;
                ldsm_x4(sb + B_X + rowA0 * 128 + (cA << 4), a0);
                ldsm_x4(sb + B_X + (rowA0 + 16) * 128 + (cA << 4), a1);
                int cB = (2 * kk + (g2 & 1)) ^ ln;
#pragma unroll
                for (int j2 = 0; j2 < 4; j2++) {
                    uint32_t b4[4];
                    int rowB = MB + j2 * 16 + (g2 >> 1) * 8 + ln;
                    ldsm_x4(sb + B_P + rowB * 128 + (cB << 4), b4);
                    mma16816(acc[2 * j2], a0, b4);
                    mma16816(acc[2 * j2 + 1], a0, b4 + 2);
                    mma16816(acc[8 + 2 * j2], a1, b4);
                    mma16816(acc[8 + 2 * j2 + 1], a1, b4 + 2);
                }
            }
#pragma unroll
            for (int lsub = 0; lsub < 2; lsub++) {
                int r0 = R0 + lsub * 16 + (lane >> 2);
#pragma unroll
                for (int j = 0; j < 8; j++) {
                    int ml = MB + j * 8 + 2 * (lane & 3);
                    const float* a = acc[lsub * 8 + j];
                    float f0 = fmaxf(a[0], 0.f) + KEPS;
                    float f1 = fmaxf(a[1], 0.f) + KEPS;
                    float f2 = fmaxf(a[2], 0.f) + KEPS;
                    float f3 = fmaxf(a[3], 0.f) + KEPS;
                    *(uint32_t*)(smem + B_F + adr512(0, r0, ml >> 3) + (ml & 7) * 2) =
                        packh2(f0, f1);
                    *(uint32_t*)(smem + B_F + adr512(0, r0 + 8, ml >> 3) + (ml & 7) * 2) =
                        packh2(f2, f3);
                    float ks0 = sKsm[ml], ks1 = sKsm[ml + 1];
                    zp[lsub][0] += f0 * ks0 + f1 * ks1;
                    zp[lsub][1] += f2 * ks0 + f3 * ks1;
                }
            }
        }
        // zp reduce (4 threads share a row)
        float* sZp = (float*)(smem + B_ZP);
#pragma unroll
        for (int lsub = 0; lsub < 2; lsub++)
#pragma unroll
            for (int rh = 0; rh < 2; rh++) {
                float z = zp[lsub][rh];
                z += __shfl_xor_sync(0xffffffffu, z, 1);
                z += __shfl_xor_sync(0xffffffffu, z, 2);
                if ((lane & 3) == 0) {
                    int row = lg * 32 + lsub * 16 + rh * 8 + (lane >> 2);
                    sZp[mb * 64 + row] = z;
                }
            }
        __syncthreads();  // F + sZp visible
        float* sZ = (float*)(smem + B_SZ);
        if (tid < 64)
            sZ[tid] = 1.0f / (sZp[tid] + sZp[64 + tid] + sZp[128 + tid] + sZp[192 + tid]);
        // out: warp 16l x 32e, K = 256
        float oacc[4][4];
#pragma unroll
        for (int n = 0; n < 4; n++)
#pragma unroll
            for (int i = 0; i < 4; i++) oacc[n][i] = 0.f;
        {
            const int rowA = lt * 16 + ln + (g2 & 1) * 8;
#pragma unroll
            for (int kk = 0; kk < 16; kk++) {
                uint32_t qh[4];
                int cA = (2 * kk + (g2 >> 1)) ^ ln;
                ldsm_x4(sb + B_F + rowA * 512 + (cA << 4), qh);
                int rowB = kk * 16 + (g2 & 1) * 8 + ln;
#pragma unroll
                for (int n2 = 0; n2 < 2; n2++) {
                    uint32_t bkv[4];
                    int cB = (eh * 4 + n2 * 2 + (g2 >> 1)) ^ ln;
                    ldsm_x4t(sb + B_KV + rowB * 128 + (cB << 4), bkv);
                    mma16816(oacc[n2 * 2], qh, bkv);
                    mma16816(oacc[n2 * 2 + 1], qh, bkv + 2);
                }
            }
        }
        __syncthreads();  // sZ visible, F consumed
        // scale + store
        const int r = lane >> 2, c2 = 2 * (lane & 3);
        const int l0 = lt * 16 + r;
        float z0 = sZ[l0], z1 = sZ[l0 + 8];
        size_t ob = tbase + (size_t)l0 * 1024;
#pragma unroll
        for (int n = 0; n < 4; n++) {
            int e = eh * 32 + n * 8 + c2;
            *(float2*)(out + ob + e) = make_float2(oacc[n][0] * z0, oacc[n][1] * z0);
            *(float2*)(out + ob + 8 * 1024 + e) = make_float2(oacc[n][2] * z1, oacc[n][3] * z1);
        }
    }
}

extern "C" void kernel_launch(void* const* d_in, const int* in_sizes, int n_in,
                              void* d_out, int out_size) {
    const float* q = (const float*)d_in[0];
    const float* k = (const float*)d_in[1];
    const float* v = (const float*)d_in[2];
    const float* P = (const float*)d_in[3];
    float* out = (float*)d_out;

    cudaFuncSetAttribute(kv_kernel, cudaFuncAttributeMaxDynamicSharedMemorySize, SMEM_A);
    cudaFuncSetAttribute(out_kernel, cudaFuncAttributeMaxDynamicSharedMemorySize, SMEM_B);

    kv_kernel<<<dim3(BH, NCHUNK, 2), 256, SMEM_A>>>(k, v, P);
    reduce_kernel<<<(BH * M * E + 255) / 256, 256>>>();
    out_kernel<<<dim3(BH, NCHUNK), 256, SMEM_B>>>(q, P, out);
}

// round 14
// speedup vs baseline: 7.8047x; 1.0766x over previous
#include <cuda_runtime.h>
#include <cuda_fp16.h>
#include <cstdint>

constexpr int B = 4, L = 4096, H = 16, D = 64, M = 256, E = 64;
constexpr int BH = 64;
constexpr int NCHUNK = 8;
constexpr float SCALE = 0.35355339059327378f;  // 64^-0.25
constexpr float KEPS = 1e-3f;
constexpr float ZEPS = 1e-6f;

// ---- global scratch ----
__device__ float g_KVpart[(size_t)NCHUNK * BH * M * E];
__device__ float g_Kspart[(size_t)NCHUNK * BH * M];
__device__ __align__(16) __half g_KVh[(size_t)BH * M * E];
__device__ float g_Ksum[(size_t)BH * M];

// ---- smem byte offsets (kernel A: M-split, 64-row tiles, cp.async stage) ----
constexpr int A_P = 0, A_STK = 16384, A_STV = 32768, A_X = 49152, A_V = 57344, A_F = 65536;
constexpr int SMEM_A = 81920;
// ---- smem byte offsets (kernel B: 64-row tiles) ----
constexpr int B_P = 0, B_X = 32768, B_F = 40960, B_KV = 73728, B_KS = 106496,
              B_ZP = 107520, B_SZ = 108544;
constexpr int SMEM_B = 108800;

// ============================ low-level helpers ============================
__device__ __forceinline__ uint32_t smem_u32(const void* p) {
    uint32_t a;
    asm("{ .reg .u64 t; cvta.to.shared.u64 t, %1; cvt.u32.u64 %0, t; }" : "=r"(a) : "l"(p));
    return a;
}
__device__ __forceinline__ void ldsm_x4(uint32_t a, uint32_t r[4]) {
    asm volatile("ldmatrix.sync.aligned.m8n8.x4.shared.b16 {%0,%1,%2,%3}, [%4];"
                 : "=r"(r[0]), "=r"(r[1]), "=r"(r[2]), "=r"(r[3]) : "r"(a));
}
__device__ __forceinline__ void ldsm_x4t(uint32_t a, uint32_t r[4]) {
    asm volatile("ldmatrix.sync.aligned.m8n8.x4.trans.shared.b16 {%0,%1,%2,%3}, [%4];"
                 : "=r"(r[0]), "=r"(r[1]), "=r"(r[2]), "=r"(r[3]) : "r"(a));
}
__device__ __forceinline__ void mma16816(float c[4], const uint32_t a[4], const uint32_t b[2]) {
    asm volatile(
        "mma.sync.aligned.m16n8k16.row.col.f32.f16.f16.f32 "
        "{%0,%1,%2,%3}, {%4,%5,%6,%7}, {%8,%9}, {%0,%1,%2,%3};"
        : "+f"(c[0]), "+f"(c[1]), "+f"(c[2]), "+f"(c[3])
        : "r"(a[0]), "r"(a[1]), "r"(a[2]), "r"(a[3]), "r"(b[0]), "r"(b[1]));
}
__device__ __forceinline__ void cp_async16(uint32_t dst, const void* src) {
    asm volatile("cp.async.cg.shared.global [%0], [%1], 16;" ::"r"(dst), "l"(src));
}
#define CP_COMMIT() asm volatile("cp.async.commit_group;" ::: "memory")
#define CP_WAIT0() asm volatile("cp.async.wait_group 0;" ::: "memory")

__device__ __forceinline__ uint32_t packh2(float x, float y) {
    __half2 h = __floats2half2_rn(x, y);
    return *(uint32_t*)&h;
}
__device__ __forceinline__ void pack_store8(float4 a, float4 b, char* hp) {
    uint4 hv;
    hv.x = packh2(a.x, a.y);
    hv.y = packh2(a.z, a.w);
    hv.z = packh2(b.x, b.y);
    hv.w = packh2(b.z, b.w);
    *(uint4*)hp = hv;
}
__device__ __forceinline__ uint32_t adr128(uint32_t base, int row, int chunk) {
    return base + row * 128 + ((chunk ^ (row & 7)) << 4);
}
__device__ __forceinline__ uint32_t adr256(uint32_t base, int row, int chunk) {
    return base + row * 256 + ((chunk ^ (row & 7)) << 4);
}
__device__ __forceinline__ uint32_t adr512(uint32_t base, int row, int chunk) {
    return base + row * 512 + ((chunk ^ (row & 7)) << 4);
}

// ============================ Kernel A: KV + Ksum partials ============================
// grid (2, BH, NCHUNK): mhalf fastest -> paired CTAs read identical k/v (L2 dedupe)
__global__ __launch_bounds__(256, 2) void kv_kernel(const float* __restrict__ k,
                                                    const float* __restrict__ v,
                                                    const float* __restrict__ P) {
    extern __shared__ char smem[];
    const uint32_t sb = smem_u32(smem);
    const int tid = threadIdx.x, w = tid >> 5, lane = tid & 31;
    const int ln = lane & 7, g2 = lane >> 3;
    const int mhalf = blockIdx.x;
    const int bh = blockIdx.y, b = bh >> 4, hd = bh & 15;
    const int chunk = blockIdx.z;
    const int lg = w & 3, quad = w >> 2;  // phi: rows lg*16, m-block quad*64 (in half)
    const int mt = w & 3, eh = w >> 2;    // KV: m mt*32, e eh*32
    const size_t cta_base = ((size_t)(b * L + chunk * 512) * H + hd) * 64;

    // prologue: stage tile 0 (64 rows of k and v, raw fp32; row stride H*D = 1024 floats)
#pragma unroll
    for (int i = 0; i < 4; i++) {
        int c = tid + i * 256;  // 0..1023 16B chunks; row = c>>4, group = c&15
        size_t off = cta_base + (size_t)(c >> 4) * 1024 + (c & 15) * 4;
        cp_async16(sb + A_STK + c * 16, k + off);
        cp_async16(sb + A_STV + c * 16, v + off);
    }
    CP_COMMIT();

    // load P half (scaled), fp16, [128 rows x 128B]
    for (int u = tid; u < 1024; u += 256) {
        int ml = u >> 3, ch = u & 7;
        int mg = mhalf * 128 + ml;
        float4 p0 = *(const float4*)(P + mg * 64 + ch * 8);
        float4 p1 = *(const float4*)(P + mg * 64 + ch * 8 + 4);
        p0.x *= SCALE; p0.y *= SCALE; p0.z *= SCALE; p0.w *= SCALE;
        p1.x *= SCALE; p1.y *= SCALE; p1.z *= SCALE; p1.w *= SCALE;
        pack_store8(p0, p1, smem + A_P + adr128(0, ml, ch));
    }

    float kvacc[2][4][4];
    float ksacc[2][4];
#pragma unroll
    for (int mf = 0; mf < 2; mf++) {
#pragma unroll
        for (int i = 0; i < 4; i++) ksacc[mf][i] = 0.f;
#pragma unroll
        for (int n = 0; n < 4; n++)
#pragma unroll
            for (int i = 0; i < 4; i++) kvacc[mf][n][i] = 0.f;
    }
    const uint32_t onesb[2] = {0x3C003C00u, 0x3C003C00u};

    for (int t = 0; t < 8; t++) {
        CP_WAIT0();
        __syncthreads();  // stage ready; F/V of t-1 consumed
        // convert stage -> fp16 X/V
#pragma unroll
        for (int i = 0; i < 2; i++) {
            int u = tid + i * 256;  // 0..511
            int l = u >> 3, ch = u & 7;
            const float* pk = (const float*)(smem + A_STK) + l * 64 + ch * 8;
            const float* pv = (const float*)(smem + A_STV) + l * 64 + ch * 8;
            pack_store8(*(const float4*)pk, *(const float4*)(pk + 4),
                        smem + A_X + adr128(0, l, ch));
            pack_store8(*(const float4*)pv, *(const float4*)(pv + 4),
                        smem + A_V + adr128(0, l, ch));
        }
        __syncthreads();  // X/V ready; stage fully consumed
        if (t + 1 < 8) {  // prefetch next tile into (now free) stage
            const size_t gbase = cta_base + (size_t)(t + 1) * 64 * 1024;
#pragma unroll
            for (int i = 0; i < 4; i++) {
                int c = tid + i * 256;
                size_t off = gbase + (size_t)(c >> 4) * 1024 + (c & 15) * 4;
                cp_async16(sb + A_STK + c * 16, k + off);
                cp_async16(sb + A_STV + c * 16, v + off);
            }
            CP_COMMIT();
        }
        // phi: warp = 16l x 64m, K=64
        {
            float acc[8][4];
#pragma unroll
            for (int j = 0; j < 8; j++)
#pragma unroll
                for (int i = 0; i < 4; i++) acc[j][i] = 0.f;
            const int rowA = lg * 16 + ln + (g2 & 1) * 8;
#pragma unroll
            for (int kk = 0; kk < 4; kk++) {
                uint32_t ah[4];
                int cA = (2 * kk + (g2 >> 1)) ^ ln;
                ldsm_x4(sb + A_X + rowA * 128 + (cA << 4), ah);
                int cB = (2 * kk + (g2 & 1)) ^ ln;
#pragma unroll
                for (int j2 = 0; j2 < 4; j2++) {
                    uint32_t b4[4];
                    int rowB = quad * 64 + j2 * 16 + (g2 >> 1) * 8 + ln;
                    ldsm_x4(sb + A_P + rowB * 128 + (cB << 4), b4);
                    mma16816(acc[2 * j2], ah, b4);
                    mma16816(acc[2 * j2 + 1], ah, b4 + 2);
                }
            }
            // relu+eps, pack to F [64 rows x 256B]
            const int r0 = lg * 16 + (lane >> 2);
#pragma unroll
            for (int j = 0; j < 8; j++) {
                int ml = quad * 64 + j * 8 + 2 * (lane & 3);
                float f0 = fmaxf(acc[j][0], 0.f) + KEPS;
                float f1 = fmaxf(acc[j][1], 0.f) + KEPS;
                float f2 = fmaxf(acc[j][2], 0.f) + KEPS;
                float f3 = fmaxf(acc[j][3], 0.f) + KEPS;
                *(uint32_t*)(smem + A_F + adr256(0, r0, ml >> 3) + (ml & 7) * 2) =
                    packh2(f0, f1);
                *(uint32_t*)(smem + A_F + adr256(0, r0 + 8, ml >> 3) + (ml & 7) * 2) =
                    packh2(f2, f3);
            }
        }
        __syncthreads();  // F visible
        // KV: kvacc += F^T @ V over 64 l-rows; ksacc += F^T @ ones
#pragma unroll
        for (int kk = 0; kk < 4; kk++) {
            uint32_t fh[2][4];
            int rowAt = kk * 16 + (g2 >> 1) * 8 + ln;
#pragma unroll
            for (int mf = 0; mf < 2; mf++) {
                int cAt = (2 * (2 * mt + mf) + (g2 & 1)) ^ ln;
                ldsm_x4t(sb + A_F + rowAt * 256 + (cAt << 4), fh[mf]);
            }
            int rowBt = kk * 16 + (g2 & 1) * 8 + ln;
            uint32_t bv[2][4];
#pragma unroll
            for (int n2 = 0; n2 < 2; n2++) {
                int cBt = (eh * 4 + n2 * 2 + (g2 >> 1)) ^ ln;
                ldsm_x4t(sb + A_V + rowBt * 128 + (cBt << 4), bv[n2]);
            }
#pragma unroll
            for (int mf = 0; mf < 2; mf++) {
                mma16816(kvacc[mf][0], fh[mf], bv[0]);
                mma16816(kvacc[mf][1], fh[mf], bv[0] + 2);
                mma16816(kvacc[mf][2], fh[mf], bv[1]);
                mma16816(kvacc[mf][3], fh[mf], bv[1] + 2);
                mma16816(ksacc[mf], fh[mf], onesb);
            }
        }
    }
    // epilogue: write this half's partials
    float* dst = g_KVpart + (size_t)(chunk * BH + bh) * M * E + mhalf * 128 * 64;
    const int r = lane >> 2, c2 = 2 * (lane & 3);
#pragma unroll
    for (int mf = 0; mf < 2; mf++)
#pragma unroll
        for (int n = 0; n < 4; n++) {
            int m0 = mt * 32 + mf * 16 + r;
            int e = eh * 32 + n * 8 + c2;
            *(float2*)(dst + m0 * 64 + e) = make_float2(kvacc[mf][n][0], kvacc[mf][n][1]);
            *(float2*)(dst + (m0 + 8) * 64 + e) = make_float2(kvacc[mf][n][2], kvacc[mf][n][3]);
        }
    if (eh == 0 && (lane & 3) == 0) {
        float* kd = g_Kspart + (size_t)(chunk * BH + bh) * M + mhalf * 128;
#pragma unroll
        for (int mf = 0; mf < 2; mf++) {
            kd[mt * 32 + mf * 16 + r] = ksacc[mf][0];
            kd[mt * 32 + mf * 16 + r + 8] = ksacc[mf][2];
        }
    }
}

// ============================ reduce: partials -> KVh fp16 + Ksum ============================
__global__ void reduce_kernel() {
    int idx = blockIdx.x * 256 + threadIdx.x;
    if (idx < BH * M * E) {
        float s = 0.f;
#pragma unroll
        for (int c = 0; c < NCHUNK; c++) s += g_KVpart[(size_t)c * BH * M * E + idx];
        g_KVh[idx] = __float2half_rn(s);
    }
    if (idx < BH * M) {
        float s = ZEPS;
#pragma unroll
        for (int c = 0; c < NCHUNK; c++) s += g_Kspart[(size_t)c * BH * M + idx];
        g_Ksum[idx] = s;
    }
}

// ============================ Kernel B: out = (Qf @ KV) * Z ============================
__global__ __launch_bounds__(256, 2) void out_kernel(const float* __restrict__ q,
                                                     const float* __restrict__ P,
                                                     float* __restrict__ out) {
    extern __shared__ char smem[];
    const uint32_t sb = smem_u32(smem);
    const int tid = threadIdx.x, w = tid >> 5, lane = tid & 31;
    const int ln = lane & 7, g2 = lane >> 3;
    const int bh = blockIdx.x, b = bh >> 4, hd = bh & 15;
    const int lg = w & 1, mb = w >> 1;  // phi: rows lg*32, m-block mb*64
    const int lt = w & 3, eh = w >> 2;  // out: rows lt*16, e eh*32
    const size_t cta_base = ((size_t)(b * L + blockIdx.y * 512) * H + hd) * 64;

    // prologue: KVh (256x64 fp16) via cp.async
#pragma unroll
    for (int i = 0; i < 8; i++) {
        int c = tid + i * 256;
        int m = c >> 3, ch = c & 7;
        cp_async16(sb + B_KV + adr128(0, m, ch), g_KVh + (size_t)bh * 16384 + c * 8);
    }
    CP_COMMIT();
    // P full (scaled) fp16 [256 rows x 128B]
    for (int u = tid; u < 2048; u += 256) {
        int m = u >> 3, ch = u & 7;
        float4 p0 = *(const float4*)(P + m * 64 + ch * 8);
        float4 p1 = *(const float4*)(P + m * 64 + ch * 8 + 4);
        p0.x *= SCALE; p0.y *= SCALE; p0.z *= SCALE; p0.w *= SCALE;
        p1.x *= SCALE; p1.y *= SCALE; p1.z *= SCALE; p1.w *= SCALE;
        pack_store8(p0, p1, smem + B_P + adr128(0, m, ch));
    }
    ((float*)(smem + B_KS))[tid] = g_Ksum[(size_t)bh * M + tid];
    const float* sKsm = (const float*)(smem + B_KS);
    CP_WAIT0();

    for (int t = 0; t < 8; t++) {
        const size_t tbase = cta_base + (size_t)t * 64 * 1024;
#pragma unroll
        for (int i = 0; i < 2; i++) {
            int c = tid + i * 256;
            int l = c >> 3, ch = c & 7;
            size_t gi = tbase + (size_t)l * 1024 + ch * 8;
            float4 x0 = *(const float4*)(q + gi);
            float4 x1 = *(const float4*)(q + gi + 4);
            pack_store8(x0, x1, smem + B_X + adr128(0, l, ch));
        }
        __syncthreads();  // X visible (KV prologue also, on t=0)
        float zp[2][2] = {{0.f, 0.f}, {0.f, 0.f}};
        {
            float acc[16][4];
#pragma unroll
            for (int j = 0; j < 16; j++)
#pragma unroll
                for (int i = 0; i < 4; i++) acc[j][i] = 0.f;
            const int R0 = lg * 32, MB = mb * 64;
            const int rowA0 = R0 + ln + (g2 & 1) * 8;
#pragma unroll
            for (int kk = 0; kk < 4; kk++) {
                uint32_t a0[4], a1[4];
                int cA = (2 * kk + (g2 >> 1)) ^ ln;
                ldsm_x4(sb + B_X + rowA0 * 128 + (cA << 4), a0);
                ldsm_x4(sb + B_X + (rowA0 + 16) * 128 + (cA << 4), a1);
                int cB = (2 * kk + (g2 & 1)) ^ ln;
#pragma unroll
                for (int j2 = 0; j2 < 4; j2++) {
                    uint32_t b4[4];
                    int rowB = MB + j2 * 16 + (g2 >> 1) * 8 + ln;
                    ldsm_x4(sb + B_P + rowB * 128 + (cB << 4), b4);
                    mma16816(acc[2 * j2], a0, b4);
                    mma16816(acc[2 * j2 + 1], a0, b4 + 2);
                    mma16816(acc[8 + 2 * j2], a1, b4);
                    mma16816(acc[8 + 2 * j2 + 1], a1, b4 + 2);
                }
            }
#pragma unroll
            for (int lsub = 0; lsub < 2; lsub++) {
                int r0 = R0 + lsub * 16 + (lane >> 2);
#pragma unroll
                for (int j = 0; j < 8; j++) {
                    int ml = MB + j * 8 + 2 * (lane & 3);
                    const float* a = acc[lsub * 8 + j];
                    float f0 = fmaxf(a[0], 0.f) + KEPS;
                    float f1 = fmaxf(a[1], 0.f) + KEPS;
                    float f2 = fmaxf(a[2], 0.f) + KEPS;
                    float f3 = fmaxf(a[3], 0.f) + KEPS;
                    *(uint32_t*)(smem + B_F + adr512(0, r0, ml >> 3) + (ml & 7) * 2) =
                        packh2(f0, f1);
                    *(uint32_t*)(smem + B_F + adr512(0, r0 + 8, ml >> 3) + (ml & 7) * 2) =
                        packh2(f2, f3);
                    float ks0 = sKsm[ml], ks1 = sKsm[ml + 1];
                    zp[lsub][0] += f0 * ks0 + f1 * ks1;
                    zp[lsub][1] += f2 * ks0 + f3 * ks1;
                }
            }
        }
        float* sZp = (float*)(smem + B_ZP);
#pragma unroll
        for (int lsub = 0; lsub < 2; lsub++)
#pragma unroll
            for (int rh = 0; rh < 2; rh++) {
                float z = zp[lsub][rh];
                z += __shfl_xor_sync(0xffffffffu, z, 1);
                z += __shfl_xor_sync(0xffffffffu, z, 2);
                if ((lane & 3) == 0) {
                    int row = lg * 32 + lsub * 16 + rh * 8 + (lane >> 2);
                    sZp[mb * 64 + row] = z;
                }
            }
        __syncthreads();  // F + sZp visible
        float* sZ = (float*)(smem + B_SZ);
        if (tid < 64)
            sZ[tid] = 1.0f / (sZp[tid] + sZp[64 + tid] + sZp[128 + tid] + sZp[192 + tid]);
        float oacc[4][4];
#pragma unroll
        for (int n = 0; n < 4; n++)
#pragma unroll
            for (int i = 0; i < 4; i++) oacc[n][i] = 0.f;
        {
            const int rowA = lt * 16 + ln + (g2 & 1) * 8;
#pragma unroll
            for (int kk = 0; kk < 16; kk++) {
                uint32_t qh[4];
                int cA = (2 * kk + (g2 >> 1)) ^ ln;
                ldsm_x4(sb + B_F + rowA * 512 + (cA << 4), qh);
                int rowB = kk * 16 + (g2 & 1) * 8 + ln;
#pragma unroll
                for (int n2 = 0; n2 < 2; n2++) {
                    uint32_t bkv[4];
                    int cB = (eh * 4 + n2 * 2 + (g2 >> 1)) ^ ln;
                    ldsm_x4t(sb + B_KV + rowB * 128 + (cB << 4), bkv);
                    mma16816(oacc[n2 * 2], qh, bkv);
                    mma16816(oacc[n2 * 2 + 1], qh, bkv + 2);
                }
            }
        }
        __syncthreads();  // sZ visible, F consumed
        const int r = lane >> 2, c2 = 2 * (lane & 3);
        const int l0 = lt * 16 + r;
        float z0 = sZ[l0], z1 = sZ[l0 + 8];
        size_t ob = tbase + (size_t)l0 * 1024;
#pragma unroll
        for (int n = 0; n < 4; n++) {
            int e = eh * 32 + n * 8 + c2;
            *(float2*)(out + ob + e) = make_float2(oacc[n][0] * z0, oacc[n][1] * z0);
            *(float2*)(out + ob + 8 * 1024 + e) = make_float2(oacc[n][2] * z1, oacc[n][3] * z1);
        }
    }
}

extern "C" void kernel_launch(void* const* d_in, const int* in_sizes, int n_in,
                              void* d_out, int out_size) {
    const float* q = (const float*)d_in[0];
    const float* k = (const float*)d_in[1];
    const float* v = (const float*)d_in[2];
    const float* P = (const float*)d_in[3];
    float* out = (float*)d_out;

    cudaFuncSetAttribute(kv_kernel, cudaFuncAttributeMaxDynamicSharedMemorySize, SMEM_A);
    cudaFuncSetAttribute(out_kernel, cudaFuncAttributeMaxDynamicSharedMemorySize, SMEM_B);

    kv_kernel<<<dim3(2, BH, NCHUNK), 256, SMEM_A>>>(k, v, P);
    reduce_kernel<<<(BH * M * E + 255) / 256, 256>>>();
    out_kernel<<<dim3(BH, NCHUNK), 256, SMEM_B>>>(q, P, out);
}